// round 1
// baseline (speedup 1.0000x reference)
#include <cuda_runtime.h>
#include <math.h>

#define D_MODEL 1024
#define NHEADS 16
#define DHEAD 64
#define BATCH 4
#define SEQL 4096
#define MROWS (BATCH*SEQL)      /* 16384 */
#define DFF (4*D_MODEL)         /* 4096  */
#define EPSLN 1e-5f
#define NCHUNK 16
#define CLEN (SEQL/NCHUNK)      /* 256   */

// ---------------- scratch (device globals; no allocation allowed) ----------
__device__ float g_y   [MROWS*D_MODEL];
__device__ float g_q   [MROWS*D_MODEL];
__device__ float g_k   [MROWS*D_MODEL];
__device__ float g_v   [MROWS*D_MODEL];
__device__ float g_g   [MROWS*D_MODEL];
__device__ float g_attn[MROWS*D_MODEL];
__device__ float g_x2  [MROWS*D_MODEL];
__device__ float g_h   [MROWS*D_MODEL];
__device__ float g_ff1 [MROWS*DFF];
__device__ float g_P   [BATCH*NHEADS*NCHUNK*DHEAD];

// ---------------- LayerNorm: one block per row, D=1024 --------------------
__global__ void ln_kernel(const float* __restrict__ x,
                          const float* __restrict__ gw,
                          const float* __restrict__ bw,
                          float* __restrict__ out) {
    int row = blockIdx.x;
    int t = threadIdx.x;                       // 256 threads, 4 elems each
    const float4* xr = (const float4*)(x + (size_t)row * D_MODEL);
    float4 v = xr[t];
    float s  = v.x + v.y + v.z + v.w;
    float ss = v.x*v.x + v.y*v.y + v.z*v.z + v.w*v.w;
    #pragma unroll
    for (int o = 16; o > 0; o >>= 1) {
        s  += __shfl_xor_sync(0xFFFFFFFFu, s,  o);
        ss += __shfl_xor_sync(0xFFFFFFFFu, ss, o);
    }
    __shared__ float red[2][8];
    int warp = t >> 5, lane = t & 31;
    if (lane == 0) { red[0][warp] = s; red[1][warp] = ss; }
    __syncthreads();
    if (t == 0) {
        float a = 0.f, c = 0.f;
        #pragma unroll
        for (int i = 0; i < 8; i++) { a += red[0][i]; c += red[1][i]; }
        float mu  = a * (1.f / D_MODEL);
        float var = c * (1.f / D_MODEL) - mu * mu;
        red[0][0] = mu;
        red[1][0] = rsqrtf(var + EPSLN);
    }
    __syncthreads();
    float mu = red[0][0], rs = red[1][0];
    float4 gv = ((const float4*)gw)[t];
    float4 bv = ((const float4*)bw)[t];
    float4 o;
    o.x = (v.x - mu) * rs * gv.x + bv.x;
    o.y = (v.y - mu) * rs * gv.y + bv.y;
    o.z = (v.z - mu) * rs * gv.z + bv.z;
    o.w = (v.w - mu) * rs * gv.w + bv.w;
    ((float4*)(out + (size_t)row * D_MODEL))[t] = o;
}

// ---------------- SGEMM 128x128x8, 256 thr, 8x8 microtile -----------------
// EPI: 0 = bias, 1 = bias+sigmoid, 2 = bias+residual, 3 = bias+exact gelu
template <int EPI>
__global__ void sgemm(const float* __restrict__ A, const float* __restrict__ Bw,
                      const float* __restrict__ bias, const float* __restrict__ Res,
                      float* __restrict__ C, int K, int N) {
    __shared__ float As[8][128];
    __shared__ float Bs[8][128];
    int tid = threadIdx.x;
    int bm = blockIdx.y * 128, bn = blockIdx.x * 128;

    int arow = tid >> 1, acol = (tid & 1) * 4;      // A: 128 rows x 8 cols
    int brow = tid >> 5, bcol = (tid & 31) * 4;     // B:   8 rows x 128 cols
    const float* Aptr = A + (size_t)(bm + arow) * K + acol;
    const float* Bptr = Bw + (size_t)brow * N + bn + bcol;

    int tx = tid & 15, ty = tid >> 4;
    float acc[8][8];
    #pragma unroll
    for (int i = 0; i < 8; i++)
        #pragma unroll
        for (int j = 0; j < 8; j++) acc[i][j] = 0.f;

    for (int k0 = 0; k0 < K; k0 += 8) {
        float4 av = *(const float4*)(Aptr + k0);
        As[acol + 0][arow] = av.x;
        As[acol + 1][arow] = av.y;
        As[acol + 2][arow] = av.z;
        As[acol + 3][arow] = av.w;
        *(float4*)&Bs[brow][bcol] = *(const float4*)(Bptr + (size_t)k0 * N);
        __syncthreads();
        #pragma unroll
        for (int k = 0; k < 8; k++) {
            float4 a0 = *(float4*)&As[k][ty * 8];
            float4 a1 = *(float4*)&As[k][ty * 8 + 4];
            float4 b0 = *(float4*)&Bs[k][tx * 8];
            float4 b1 = *(float4*)&Bs[k][tx * 8 + 4];
            float ar[8] = {a0.x, a0.y, a0.z, a0.w, a1.x, a1.y, a1.z, a1.w};
            float br[8] = {b0.x, b0.y, b0.z, b0.w, b1.x, b1.y, b1.z, b1.w};
            #pragma unroll
            for (int i = 0; i < 8; i++)
                #pragma unroll
                for (int j = 0; j < 8; j++)
                    acc[i][j] += ar[i] * br[j];
        }
        __syncthreads();
    }

    #pragma unroll
    for (int i = 0; i < 8; i++) {
        int m = bm + ty * 8 + i;
        #pragma unroll
        for (int j = 0; j < 8; j += 4) {
            int n = bn + tx * 8 + j;
            float4 bb = *(const float4*)(bias + n);
            float4 r;
            r.x = acc[i][j + 0] + bb.x;
            r.y = acc[i][j + 1] + bb.y;
            r.z = acc[i][j + 2] + bb.z;
            r.w = acc[i][j + 3] + bb.w;
            if (EPI == 1) {
                r.x = 1.f / (1.f + expf(-r.x));
                r.y = 1.f / (1.f + expf(-r.y));
                r.z = 1.f / (1.f + expf(-r.z));
                r.w = 1.f / (1.f + expf(-r.w));
            } else if (EPI == 2) {
                float4 rr = *(const float4*)(Res + (size_t)m * N + n);
                r.x += rr.x; r.y += rr.y; r.z += rr.z; r.w += rr.w;
            } else if (EPI == 3) {
                const float c = 0.70710678118654752f;
                r.x = 0.5f * r.x * (1.f + erff(r.x * c));
                r.y = 0.5f * r.y * (1.f + erff(r.y * c));
                r.z = 0.5f * r.z * (1.f + erff(r.z * c));
                r.w = 0.5f * r.w * (1.f + erff(r.w * c));
            }
            *(float4*)(C + (size_t)m * N + n) = r;
        }
    }
}

// ---------------- Retention scan (chunked associative scan) ---------------
// unit = ((b*NHEADS + h)*NCHUNK + chunk); 1024 units, 64 lanes (d) each.
__device__ __forceinline__ void unit_decompose(int tid, int bx,
                                               int& b, int& h, int& chunk, int& d) {
    d = tid & 63;
    int unit = bx * 4 + (tid >> 6);
    chunk = unit & (NCHUNK - 1);
    int bh = unit >> 4;          // NCHUNK == 16
    h = bh & (NHEADS - 1);
    b = bh >> 4;                 // NHEADS == 16
}

__global__ void scan_partial(const float* __restrict__ dlogit) {
    int b, h, chunk, d;
    unit_decompose(threadIdx.x, blockIdx.x, b, h, chunk, d);
    float decay = 1.f / (1.f + expf(-dlogit[h]));
    float p = 0.f;
    size_t base = ((size_t)(b * SEQL + chunk * CLEN)) * D_MODEL + h * DHEAD + d;
    #pragma unroll 4
    for (int i = 0; i < CLEN; i++) {
        size_t idx = base + (size_t)i * D_MODEL;
        p = decay * p + g_k[idx] * g_v[idx];
    }
    int bh = b * NHEADS + h;
    g_P[(bh * NCHUNK + chunk) * DHEAD + d] = p;
}

__global__ void scan_final(const float* __restrict__ dlogit) {
    int b, h, chunk, d;
    unit_decompose(threadIdx.x, blockIdx.x, b, h, chunk, d);
    float decay = 1.f / (1.f + expf(-dlogit[h]));
    float dCL = powf(decay, (float)CLEN);
    int bh = b * NHEADS + h;
    float s = 0.f;
    for (int j = 0; j < chunk; j++)
        s = dCL * s + g_P[(bh * NCHUNK + j) * DHEAD + d];
    const float scale = 0.125f;   // DHEAD^-0.5
    size_t base = ((size_t)(b * SEQL + chunk * CLEN)) * D_MODEL + h * DHEAD + d;
    #pragma unroll 4
    for (int i = 0; i < CLEN; i++) {
        size_t idx = base + (size_t)i * D_MODEL;
        s = decay * s + g_k[idx] * g_v[idx];
        g_attn[idx] = g_g[idx] * g_q[idx] * s * scale;
    }
}

// ---------------- launch ---------------------------------------------------
extern "C" void kernel_launch(void* const* d_in, const int* in_sizes, int n_in,
                              void* d_out, int out_size) {
    const float* x      = (const float*)d_in[0];
    const float* ln1_g  = (const float*)d_in[1];
    const float* ln1_b  = (const float*)d_in[2];
    const float* Wq     = (const float*)d_in[3];
    const float* bq     = (const float*)d_in[4];
    const float* Wk     = (const float*)d_in[5];
    const float* bk     = (const float*)d_in[6];
    const float* Wv     = (const float*)d_in[7];
    const float* bv     = (const float*)d_in[8];
    const float* Wg     = (const float*)d_in[9];
    const float* bg     = (const float*)d_in[10];
    const float* dlogit = (const float*)d_in[11];
    const float* Wo     = (const float*)d_in[12];
    const float* bo     = (const float*)d_in[13];
    const float* ln2_g  = (const float*)d_in[14];
    const float* ln2_b  = (const float*)d_in[15];
    const float* W1     = (const float*)d_in[16];
    const float* b1     = (const float*)d_in[17];
    const float* W2     = (const float*)d_in[18];
    const float* b2     = (const float*)d_in[19];
    float* out = (float*)d_out;

    float *y, *q, *k, *v, *g, *attn, *x2, *h, *ff1;
    cudaGetSymbolAddress((void**)&y,    g_y);
    cudaGetSymbolAddress((void**)&q,    g_q);
    cudaGetSymbolAddress((void**)&k,    g_k);
    cudaGetSymbolAddress((void**)&v,    g_v);
    cudaGetSymbolAddress((void**)&g,    g_g);
    cudaGetSymbolAddress((void**)&attn, g_attn);
    cudaGetSymbolAddress((void**)&x2,   g_x2);
    cudaGetSymbolAddress((void**)&h,    g_h);
    cudaGetSymbolAddress((void**)&ff1,  g_ff1);

    dim3 gD(D_MODEL / 128, MROWS / 128);   // 8 x 128
    dim3 gF(DFF / 128,     MROWS / 128);   // 32 x 128

    ln_kernel<<<MROWS, 256>>>(x, ln1_g, ln1_b, y);

    sgemm<0><<<gD, 256>>>(y, Wq, bq, nullptr, q, D_MODEL, D_MODEL);
    sgemm<0><<<gD, 256>>>(y, Wk, bk, nullptr, k, D_MODEL, D_MODEL);
    sgemm<0><<<gD, 256>>>(y, Wv, bv, nullptr, v, D_MODEL, D_MODEL);
    sgemm<1><<<gD, 256>>>(y, Wg, bg, nullptr, g, D_MODEL, D_MODEL);

    scan_partial<<<256, 256>>>(dlogit);
    scan_final  <<<256, 256>>>(dlogit);

    sgemm<2><<<gD, 256>>>(attn, Wo, bo, x, x2, D_MODEL, D_MODEL);

    ln_kernel<<<MROWS, 256>>>(x2, ln2_g, ln2_b, h);

    sgemm<3><<<gF, 256>>>(h,   W1, b1, nullptr, ff1, D_MODEL, DFF);
    sgemm<2><<<gD, 256>>>(ff1, W2, b2, x2,      out, DFF,     D_MODEL);
}

// round 3
// speedup vs baseline: 2.9559x; 2.9559x over previous
#include <cuda_runtime.h>
#include <math.h>
#include <stdint.h>

#define D_MODEL 1024
#define NHEADS 16
#define DHEAD 64
#define BATCH 4
#define SEQL 4096
#define MROWS (BATCH*SEQL)      /* 16384 */
#define DFF (4*D_MODEL)         /* 4096  */
#define EPSLN 1e-5f
#define NCHUNK 16
#define CLEN (SEQL/NCHUNK)      /* 256   */

// ---------------- scratch (device globals; no allocation allowed) ----------
__device__ float g_y   [MROWS*D_MODEL];
__device__ float g_q   [MROWS*D_MODEL];
__device__ float g_k   [MROWS*D_MODEL];
__device__ float g_v   [MROWS*D_MODEL];
__device__ float g_g   [MROWS*D_MODEL];
__device__ float g_attn[MROWS*D_MODEL];
__device__ float g_x2  [MROWS*D_MODEL];
__device__ float g_h   [MROWS*D_MODEL];
__device__ float g_ff1 [MROWS*DFF];
__device__ float g_P   [BATCH*NHEADS*NCHUNK*DHEAD];

// ---------------- LayerNorm: one block per row, D=1024 --------------------
__global__ void ln_kernel(const float* __restrict__ x,
                          const float* __restrict__ gw,
                          const float* __restrict__ bw,
                          float* __restrict__ out) {
    int row = blockIdx.x;
    int t = threadIdx.x;                       // 256 threads, 4 elems each
    const float4* xr = (const float4*)(x + (size_t)row * D_MODEL);
    float4 v = xr[t];
    float s  = v.x + v.y + v.z + v.w;
    float ss = v.x*v.x + v.y*v.y + v.z*v.z + v.w*v.w;
    #pragma unroll
    for (int o = 16; o > 0; o >>= 1) {
        s  += __shfl_xor_sync(0xFFFFFFFFu, s,  o);
        ss += __shfl_xor_sync(0xFFFFFFFFu, ss, o);
    }
    __shared__ float red[2][8];
    int warp = t >> 5, lane = t & 31;
    if (lane == 0) { red[0][warp] = s; red[1][warp] = ss; }
    __syncthreads();
    if (t == 0) {
        float a = 0.f, c = 0.f;
        #pragma unroll
        for (int i = 0; i < 8; i++) { a += red[0][i]; c += red[1][i]; }
        float mu  = a * (1.f / D_MODEL);
        float var = c * (1.f / D_MODEL) - mu * mu;
        red[0][0] = mu;
        red[1][0] = rsqrtf(var + EPSLN);
    }
    __syncthreads();
    float mu = red[0][0], rs = red[1][0];
    float4 gv = ((const float4*)gw)[t];
    float4 bv = ((const float4*)bw)[t];
    float4 o;
    o.x = (v.x - mu) * rs * gv.x + bv.x;
    o.y = (v.y - mu) * rs * gv.y + bv.y;
    o.z = (v.z - mu) * rs * gv.z + bv.z;
    o.w = (v.w - mu) * rs * gv.w + bv.w;
    ((float4*)(out + (size_t)row * D_MODEL))[t] = o;
}

// ---------------- TF32 tensor-core GEMM -----------------------------------
// 128x128 block tile, BK=16, 256 threads (8 warps, 2x4), warp tile 64x32,
// mma.sync.m16n8k8.tf32, cp.async double buffering.
// EPI: 0 = bias, 1 = bias+sigmoid, 2 = bias+residual, 3 = bias+exact gelu

#define CP16(dst, src) asm volatile( \
    "cp.async.cg.shared.global [%0], [%1], 16;\n" :: "r"(dst), "l"(src))

__device__ __forceinline__ uint32_t f2tf32(float f) {
    uint32_t u;
    asm("cvt.rna.tf32.f32 %0, %1;" : "=r"(u) : "f"(f));
    return u;
}

template <int EPI>
__global__ __launch_bounds__(256) void tgemm(
        const float* __restrict__ A, const float* __restrict__ Bw,
        const float* __restrict__ bias, const float* __restrict__ Res,
        float* __restrict__ C, int K, int N) {
    __shared__ float As[2][128][20];   // [m][k] pad->20 (80B rows, 16B-aligned)
    __shared__ float Bs[2][16][136];   // [k][n] pad->136 (544B rows)

    int tid  = threadIdx.x;
    int bm   = blockIdx.y * 128, bn = blockIdx.x * 128;
    int warp = tid >> 5, lane = tid & 31;
    int wm   = (warp >> 2) * 64;       // warp M offset (0/64)
    int wn   = (warp & 3) * 32;        // warp N offset (0/32/64/96)
    int gid  = lane >> 2, ctig = lane & 3;

    int a_m = tid >> 1, a_k = (tid & 1) * 8;
    int b_k = tid >> 4, b_n = (tid & 15) * 8;
    const float* Ag = A  + (size_t)(bm + a_m) * K + a_k;
    const float* Bg = Bw + (size_t)b_k * N + bn + b_n;

    float acc[4][4][4];
    #pragma unroll
    for (int i = 0; i < 4; i++)
        #pragma unroll
        for (int j = 0; j < 4; j++)
            #pragma unroll
            for (int r = 0; r < 4; r++) acc[i][j][r] = 0.f;

    // prologue: stage 0
    {
        uint32_t d0 = (uint32_t)__cvta_generic_to_shared(&As[0][a_m][a_k]);
        CP16(d0, Ag); CP16(d0 + 16, Ag + 4);
        uint32_t d1 = (uint32_t)__cvta_generic_to_shared(&Bs[0][b_k][b_n]);
        CP16(d1, Bg); CP16(d1 + 16, Bg + 4);
        asm volatile("cp.async.commit_group;\n");
    }

    int buf = 0;
    for (int k0 = 0; k0 < K; k0 += 16) {
        asm volatile("cp.async.wait_group 0;\n");
        __syncthreads();
        if (k0 + 16 < K) {
            int nb = buf ^ 1, kn = k0 + 16;
            uint32_t d0 = (uint32_t)__cvta_generic_to_shared(&As[nb][a_m][a_k]);
            CP16(d0, Ag + kn); CP16(d0 + 16, Ag + kn + 4);
            uint32_t d1 = (uint32_t)__cvta_generic_to_shared(&Bs[nb][b_k][b_n]);
            const float* bsrc = Bg + (size_t)kn * N;
            CP16(d1, bsrc); CP16(d1 + 16, bsrc + 4);
            asm volatile("cp.async.commit_group;\n");
        }
        #pragma unroll
        for (int ks = 0; ks < 16; ks += 8) {
            uint32_t af[4][4], bf[4][2];
            #pragma unroll
            for (int im = 0; im < 4; im++) {
                int m0 = wm + im * 16 + gid;
                af[im][0] = f2tf32(As[buf][m0    ][ks + ctig]);
                af[im][1] = f2tf32(As[buf][m0 + 8][ks + ctig]);
                af[im][2] = f2tf32(As[buf][m0    ][ks + ctig + 4]);
                af[im][3] = f2tf32(As[buf][m0 + 8][ks + ctig + 4]);
            }
            #pragma unroll
            for (int jn = 0; jn < 4; jn++) {
                int n0 = wn + jn * 8 + gid;
                bf[jn][0] = f2tf32(Bs[buf][ks + ctig    ][n0]);
                bf[jn][1] = f2tf32(Bs[buf][ks + ctig + 4][n0]);
            }
            #pragma unroll
            for (int im = 0; im < 4; im++)
                #pragma unroll
                for (int jn = 0; jn < 4; jn++) {
                    asm volatile(
                        "mma.sync.aligned.m16n8k8.row.col.f32.tf32.tf32.f32 "
                        "{%0,%1,%2,%3}, {%4,%5,%6,%7}, {%8,%9}, {%0,%1,%2,%3};\n"
                        : "+f"(acc[im][jn][0]), "+f"(acc[im][jn][1]),
                          "+f"(acc[im][jn][2]), "+f"(acc[im][jn][3])
                        : "r"(af[im][0]), "r"(af[im][1]),
                          "r"(af[im][2]), "r"(af[im][3]),
                          "r"(bf[jn][0]), "r"(bf[jn][1]));
                }
        }
        buf ^= 1;
    }

    // epilogue
    #pragma unroll
    for (int im = 0; im < 4; im++) {
        #pragma unroll
        for (int jn = 0; jn < 4; jn++) {
            int m = bm + wm + im * 16 + gid;
            int n = bn + wn + jn * 8 + ctig * 2;
            float2 bb = *(const float2*)(bias + n);
            float v0 = acc[im][jn][0] + bb.x;
            float v1 = acc[im][jn][1] + bb.y;
            float v2 = acc[im][jn][2] + bb.x;
            float v3 = acc[im][jn][3] + bb.y;
            if (EPI == 1) {
                v0 = 1.f / (1.f + expf(-v0));
                v1 = 1.f / (1.f + expf(-v1));
                v2 = 1.f / (1.f + expf(-v2));
                v3 = 1.f / (1.f + expf(-v3));
            } else if (EPI == 2) {
                float2 r0 = *(const float2*)(Res + (size_t)m * N + n);
                float2 r1 = *(const float2*)(Res + (size_t)(m + 8) * N + n);
                v0 += r0.x; v1 += r0.y; v2 += r1.x; v3 += r1.y;
            } else if (EPI == 3) {
                const float c = 0.70710678118654752f;
                v0 = 0.5f * v0 * (1.f + erff(v0 * c));
                v1 = 0.5f * v1 * (1.f + erff(v1 * c));
                v2 = 0.5f * v2 * (1.f + erff(v2 * c));
                v3 = 0.5f * v3 * (1.f + erff(v3 * c));
            }
            *(float2*)(C + (size_t)m * N + n)       = make_float2(v0, v1);
            *(float2*)(C + (size_t)(m + 8) * N + n) = make_float2(v2, v3);
        }
    }
}

// ---------------- Retention scan (chunked associative scan) ---------------
__device__ __forceinline__ void unit_decompose(int tid, int bx,
                                               int& b, int& h, int& chunk, int& d) {
    d = tid & 63;
    int unit = bx * 4 + (tid >> 6);
    chunk = unit & (NCHUNK - 1);
    int bh = unit >> 4;
    h = bh & (NHEADS - 1);
    b = bh >> 4;
}

__global__ void scan_partial(const float* __restrict__ dlogit) {
    int b, h, chunk, d;
    unit_decompose(threadIdx.x, blockIdx.x, b, h, chunk, d);
    float decay = 1.f / (1.f + expf(-dlogit[h]));
    float p = 0.f;
    size_t base = ((size_t)(b * SEQL + chunk * CLEN)) * D_MODEL + h * DHEAD + d;
    #pragma unroll 4
    for (int i = 0; i < CLEN; i++) {
        size_t idx = base + (size_t)i * D_MODEL;
        p = decay * p + g_k[idx] * g_v[idx];
    }
    int bh = b * NHEADS + h;
    g_P[(bh * NCHUNK + chunk) * DHEAD + d] = p;
}

__global__ void scan_final(const float* __restrict__ dlogit) {
    int b, h, chunk, d;
    unit_decompose(threadIdx.x, blockIdx.x, b, h, chunk, d);
    float decay = 1.f / (1.f + expf(-dlogit[h]));
    float dCL = powf(decay, (float)CLEN);
    int bh = b * NHEADS + h;
    float s = 0.f;
    for (int j = 0; j < chunk; j++)
        s = dCL * s + g_P[(bh * NCHUNK + j) * DHEAD + d];
    const float scale = 0.125f;   // DHEAD^-0.5
    size_t base = ((size_t)(b * SEQL + chunk * CLEN)) * D_MODEL + h * DHEAD + d;
    #pragma unroll 4
    for (int i = 0; i < CLEN; i++) {
        size_t idx = base + (size_t)i * D_MODEL;
        s = decay * s + g_k[idx] * g_v[idx];
        g_attn[idx] = g_g[idx] * g_q[idx] * s * scale;
    }
}

// ---------------- launch ---------------------------------------------------
extern "C" void kernel_launch(void* const* d_in, const int* in_sizes, int n_in,
                              void* d_out, int out_size) {
    const float* x      = (const float*)d_in[0];
    const float* ln1_g  = (const float*)d_in[1];
    const float* ln1_b  = (const float*)d_in[2];
    const float* Wq     = (const float*)d_in[3];
    const float* bq     = (const float*)d_in[4];
    const float* Wk     = (const float*)d_in[5];
    const float* bk     = (const float*)d_in[6];
    const float* Wv     = (const float*)d_in[7];
    const float* bv     = (const float*)d_in[8];
    const float* Wg     = (const float*)d_in[9];
    const float* bg     = (const float*)d_in[10];
    const float* dlogit = (const float*)d_in[11];
    const float* Wo     = (const float*)d_in[12];
    const float* bo     = (const float*)d_in[13];
    const float* ln2_g  = (const float*)d_in[14];
    const float* ln2_b  = (const float*)d_in[15];
    const float* W1     = (const float*)d_in[16];
    const float* b1     = (const float*)d_in[17];
    const float* W2     = (const float*)d_in[18];
    const float* b2     = (const float*)d_in[19];
    float* out = (float*)d_out;

    float *y, *q, *k, *v, *g, *attn, *x2, *h, *ff1;
    cudaGetSymbolAddress((void**)&y,    g_y);
    cudaGetSymbolAddress((void**)&q,    g_q);
    cudaGetSymbolAddress((void**)&k,    g_k);
    cudaGetSymbolAddress((void**)&v,    g_v);
    cudaGetSymbolAddress((void**)&g,    g_g);
    cudaGetSymbolAddress((void**)&attn, g_attn);
    cudaGetSymbolAddress((void**)&x2,   g_x2);
    cudaGetSymbolAddress((void**)&h,    g_h);
    cudaGetSymbolAddress((void**)&ff1,  g_ff1);

    dim3 gD(D_MODEL / 128, MROWS / 128);   // 8 x 128
    dim3 gF(DFF / 128,     MROWS / 128);   // 32 x 128

    ln_kernel<<<MROWS, 256>>>(x, ln1_g, ln1_b, y);

    tgemm<0><<<gD, 256>>>(y, Wq, bq, nullptr, q, D_MODEL, D_MODEL);
    tgemm<0><<<gD, 256>>>(y, Wk, bk, nullptr, k, D_MODEL, D_MODEL);
    tgemm<0><<<gD, 256>>>(y, Wv, bv, nullptr, v, D_MODEL, D_MODEL);
    tgemm<1><<<gD, 256>>>(y, Wg, bg, nullptr, g, D_MODEL, D_MODEL);

    scan_partial<<<256, 256>>>(dlogit);
    scan_final  <<<256, 256>>>(dlogit);

    tgemm<2><<<gD, 256>>>(attn, Wo, bo, x, x2, D_MODEL, D_MODEL);

    ln_kernel<<<MROWS, 256>>>(x2, ln2_g, ln2_b, h);

    tgemm<3><<<gF, 256>>>(h,   W1, b1, nullptr, ff1, D_MODEL, DFF);
    tgemm<2><<<gD, 256>>>(ff1, W2, b2, x2,      out, DFF,     D_MODEL);
}

// round 4
// speedup vs baseline: 2.9933x; 1.0126x over previous
#include <cuda_runtime.h>
#include <math.h>
#include <stdint.h>

#define D_MODEL 1024
#define NHEADS 16
#define DHEAD 64
#define BATCH 4
#define SEQL 4096
#define MROWS (BATCH*SEQL)      /* 16384 */
#define DFF (4*D_MODEL)         /* 4096  */
#define EPSLN 1e-5f
#define NCHUNK 16
#define CLEN (SEQL/NCHUNK)      /* 256   */

// ---------------- scratch (device globals; no allocation allowed) ----------
__device__ float g_y   [MROWS*D_MODEL];
__device__ float g_q   [MROWS*D_MODEL];
__device__ float g_k   [MROWS*D_MODEL];
__device__ float g_v   [MROWS*D_MODEL];
__device__ float g_g   [MROWS*D_MODEL];
__device__ float g_attn[MROWS*D_MODEL];
__device__ float g_x2  [MROWS*D_MODEL];
__device__ float g_h   [MROWS*D_MODEL];
__device__ float g_ff1 [MROWS*DFF];
__device__ float g_P   [BATCH*NHEADS*NCHUNK*DHEAD];

// ---------------- LayerNorm: one block per row, D=1024 --------------------
__global__ void ln_kernel(const float* __restrict__ x,
                          const float* __restrict__ gw,
                          const float* __restrict__ bw,
                          float* __restrict__ out) {
    int row = blockIdx.x;
    int t = threadIdx.x;                       // 256 threads, 4 elems each
    const float4* xr = (const float4*)(x + (size_t)row * D_MODEL);
    float4 v = xr[t];
    float s  = v.x + v.y + v.z + v.w;
    float ss = v.x*v.x + v.y*v.y + v.z*v.z + v.w*v.w;
    #pragma unroll
    for (int o = 16; o > 0; o >>= 1) {
        s  += __shfl_xor_sync(0xFFFFFFFFu, s,  o);
        ss += __shfl_xor_sync(0xFFFFFFFFu, ss, o);
    }
    __shared__ float red[2][8];
    int warp = t >> 5, lane = t & 31;
    if (lane == 0) { red[0][warp] = s; red[1][warp] = ss; }
    __syncthreads();
    if (t == 0) {
        float a = 0.f, c = 0.f;
        #pragma unroll
        for (int i = 0; i < 8; i++) { a += red[0][i]; c += red[1][i]; }
        float mu  = a * (1.f / D_MODEL);
        float var = c * (1.f / D_MODEL) - mu * mu;
        red[0][0] = mu;
        red[1][0] = rsqrtf(var + EPSLN);
    }
    __syncthreads();
    float mu = red[0][0], rs = red[1][0];
    float4 gv = ((const float4*)gw)[t];
    float4 bv = ((const float4*)bw)[t];
    float4 o;
    o.x = (v.x - mu) * rs * gv.x + bv.x;
    o.y = (v.y - mu) * rs * gv.y + bv.y;
    o.z = (v.z - mu) * rs * gv.z + bv.z;
    o.w = (v.w - mu) * rs * gv.w + bv.w;
    ((float4*)(out + (size_t)row * D_MODEL))[t] = o;
}

// ---------------- TF32 tensor-core GEMM -----------------------------------
// 128x128 block tile, BK=16, 256 threads (8 warps, 2x4), warp tile 64x32,
// mma.sync.m16n8k8.tf32, 3-stage cp.async pipeline, raw-fp32-as-tf32 (HW
// truncates the low 13 bits; no explicit cvt).
// EPI: 0 = bias, 1 = bias+sigmoid, 2 = bias+residual, 3 = bias+exact gelu

#define CP16(dst, src) asm volatile( \
    "cp.async.cg.shared.global [%0], [%1], 16;\n" :: "r"(dst), "l"(src))

template <int EPI>
__global__ __launch_bounds__(256) void tgemm(
        const float* __restrict__ A, const float* __restrict__ Bw,
        const float* __restrict__ bias, const float* __restrict__ Res,
        float* __restrict__ C, int K, int N) {
    __shared__ float As[3][128][20];   // [stage][m][k] pad->20
    __shared__ float Bs[3][16][136];   // [stage][k][n] pad->136

    int tid  = threadIdx.x;
    int bm   = blockIdx.y * 128, bn = blockIdx.x * 128;
    int warp = tid >> 5, lane = tid & 31;
    int wm   = (warp >> 2) * 64;       // warp M offset (0/64)
    int wn   = (warp & 3) * 32;        // warp N offset (0/32/64/96)
    int gid  = lane >> 2, ctig = lane & 3;

    int a_m = tid >> 1, a_k = (tid & 1) * 8;
    int b_k = tid >> 4, b_n = (tid & 15) * 8;
    const float* Ag = A  + (size_t)(bm + a_m) * K + a_k;
    const float* Bg = Bw + (size_t)b_k * N + bn + b_n;

    float acc[4][4][4];
    #pragma unroll
    for (int i = 0; i < 4; i++)
        #pragma unroll
        for (int j = 0; j < 4; j++)
            #pragma unroll
            for (int r = 0; r < 4; r++) acc[i][j][r] = 0.f;

    int ntiles = K >> 4;

    // prologue: stages 0 and 1
    #pragma unroll
    for (int p = 0; p < 2; p++) {
        int kk = p * 16;
        uint32_t d0 = (uint32_t)__cvta_generic_to_shared(&As[p][a_m][a_k]);
        CP16(d0, Ag + kk); CP16(d0 + 16, Ag + kk + 4);
        uint32_t d1 = (uint32_t)__cvta_generic_to_shared(&Bs[p][b_k][b_n]);
        const float* bsrc = Bg + (size_t)kk * N;
        CP16(d1, bsrc); CP16(d1 + 16, bsrc + 4);
        asm volatile("cp.async.commit_group;\n");
    }

    int st = 0, pst = 2;   // compute stage, prefetch stage
    for (int t = 0; t < ntiles; t++) {
        asm volatile("cp.async.wait_group 1;\n");
        __syncthreads();
        if (t + 2 < ntiles) {
            int kn = (t + 2) * 16;
            uint32_t d0 = (uint32_t)__cvta_generic_to_shared(&As[pst][a_m][a_k]);
            CP16(d0, Ag + kn); CP16(d0 + 16, Ag + kn + 4);
            uint32_t d1 = (uint32_t)__cvta_generic_to_shared(&Bs[pst][b_k][b_n]);
            const float* bsrc = Bg + (size_t)kn * N;
            CP16(d1, bsrc); CP16(d1 + 16, bsrc + 4);
            asm volatile("cp.async.commit_group;\n");
        } else {
            asm volatile("cp.async.commit_group;\n");   // keep group count in lockstep
        }

        const float (* __restrict__ Ab)[20]  = As[st];
        const float (* __restrict__ Bb)[136] = Bs[st];
        #pragma unroll
        for (int ks = 0; ks < 16; ks += 8) {
            uint32_t af[4][4], bf[4][2];
            #pragma unroll
            for (int im = 0; im < 4; im++) {
                int m0 = wm + im * 16 + gid;
                af[im][0] = __float_as_uint(Ab[m0    ][ks + ctig]);
                af[im][1] = __float_as_uint(Ab[m0 + 8][ks + ctig]);
                af[im][2] = __float_as_uint(Ab[m0    ][ks + ctig + 4]);
                af[im][3] = __float_as_uint(Ab[m0 + 8][ks + ctig + 4]);
            }
            #pragma unroll
            for (int jn = 0; jn < 4; jn++) {
                int n0 = wn + jn * 8 + gid;
                bf[jn][0] = __float_as_uint(Bb[ks + ctig    ][n0]);
                bf[jn][1] = __float_as_uint(Bb[ks + ctig + 4][n0]);
            }
            #pragma unroll
            for (int im = 0; im < 4; im++)
                #pragma unroll
                for (int jn = 0; jn < 4; jn++) {
                    asm volatile(
                        "mma.sync.aligned.m16n8k8.row.col.f32.tf32.tf32.f32 "
                        "{%0,%1,%2,%3}, {%4,%5,%6,%7}, {%8,%9}, {%0,%1,%2,%3};\n"
                        : "+f"(acc[im][jn][0]), "+f"(acc[im][jn][1]),
                          "+f"(acc[im][jn][2]), "+f"(acc[im][jn][3])
                        : "r"(af[im][0]), "r"(af[im][1]),
                          "r"(af[im][2]), "r"(af[im][3]),
                          "r"(bf[jn][0]), "r"(bf[jn][1]));
                }
        }
        st = (st + 1) % 3;
        pst = (pst + 1) % 3;
    }

    // epilogue
    #pragma unroll
    for (int im = 0; im < 4; im++) {
        #pragma unroll
        for (int jn = 0; jn < 4; jn++) {
            int m = bm + wm + im * 16 + gid;
            int n = bn + wn + jn * 8 + ctig * 2;
            float2 bb = *(const float2*)(bias + n);
            float v0 = acc[im][jn][0] + bb.x;
            float v1 = acc[im][jn][1] + bb.y;
            float v2 = acc[im][jn][2] + bb.x;
            float v3 = acc[im][jn][3] + bb.y;
            if (EPI == 1) {
                v0 = 1.f / (1.f + expf(-v0));
                v1 = 1.f / (1.f + expf(-v1));
                v2 = 1.f / (1.f + expf(-v2));
                v3 = 1.f / (1.f + expf(-v3));
            } else if (EPI == 2) {
                float2 r0 = *(const float2*)(Res + (size_t)m * N + n);
                float2 r1 = *(const float2*)(Res + (size_t)(m + 8) * N + n);
                v0 += r0.x; v1 += r0.y; v2 += r1.x; v3 += r1.y;
            } else if (EPI == 3) {
                const float c = 0.70710678118654752f;
                v0 = 0.5f * v0 * (1.f + erff(v0 * c));
                v1 = 0.5f * v1 * (1.f + erff(v1 * c));
                v2 = 0.5f * v2 * (1.f + erff(v2 * c));
                v3 = 0.5f * v3 * (1.f + erff(v3 * c));
            }
            *(float2*)(C + (size_t)m * N + n)       = make_float2(v0, v1);
            *(float2*)(C + (size_t)(m + 8) * N + n) = make_float2(v2, v3);
        }
    }
}

// ---------------- Retention scan (chunked associative scan) ---------------
__device__ __forceinline__ void unit_decompose(int tid, int bx,
                                               int& b, int& h, int& chunk, int& d) {
    d = tid & 63;
    int unit = bx * 4 + (tid >> 6);
    chunk = unit & (NCHUNK - 1);
    int bh = unit >> 4;
    h = bh & (NHEADS - 1);
    b = bh >> 4;
}

__global__ void scan_partial(const float* __restrict__ dlogit) {
    int b, h, chunk, d;
    unit_decompose(threadIdx.x, blockIdx.x, b, h, chunk, d);
    float decay = 1.f / (1.f + expf(-dlogit[h]));
    float p = 0.f;
    size_t base = ((size_t)(b * SEQL + chunk * CLEN)) * D_MODEL + h * DHEAD + d;
    #pragma unroll 4
    for (int i = 0; i < CLEN; i++) {
        size_t idx = base + (size_t)i * D_MODEL;
        p = decay * p + g_k[idx] * g_v[idx];
    }
    int bh = b * NHEADS + h;
    g_P[(bh * NCHUNK + chunk) * DHEAD + d] = p;
}

__global__ void scan_final(const float* __restrict__ dlogit) {
    int b, h, chunk, d;
    unit_decompose(threadIdx.x, blockIdx.x, b, h, chunk, d);
    float decay = 1.f / (1.f + expf(-dlogit[h]));
    float dCL = powf(decay, (float)CLEN);
    int bh = b * NHEADS + h;
    float s = 0.f;
    for (int j = 0; j < chunk; j++)
        s = dCL * s + g_P[(bh * NCHUNK + j) * DHEAD + d];
    const float scale = 0.125f;   // DHEAD^-0.5
    size_t base = ((size_t)(b * SEQL + chunk * CLEN)) * D_MODEL + h * DHEAD + d;
    #pragma unroll 4
    for (int i = 0; i < CLEN; i++) {
        size_t idx = base + (size_t)i * D_MODEL;
        s = decay * s + g_k[idx] * g_v[idx];
        g_attn[idx] = g_g[idx] * g_q[idx] * s * scale;
    }
}

// ---------------- launch ---------------------------------------------------
extern "C" void kernel_launch(void* const* d_in, const int* in_sizes, int n_in,
                              void* d_out, int out_size) {
    const float* x      = (const float*)d_in[0];
    const float* ln1_g  = (const float*)d_in[1];
    const float* ln1_b  = (const float*)d_in[2];
    const float* Wq     = (const float*)d_in[3];
    const float* bq     = (const float*)d_in[4];
    const float* Wk     = (const float*)d_in[5];
    const float* bk     = (const float*)d_in[6];
    const float* Wv     = (const float*)d_in[7];
    const float* bv     = (const float*)d_in[8];
    const float* Wg     = (const float*)d_in[9];
    const float* bg     = (const float*)d_in[10];
    const float* dlogit = (const float*)d_in[11];
    const float* Wo     = (const float*)d_in[12];
    const float* bo     = (const float*)d_in[13];
    const float* ln2_g  = (const float*)d_in[14];
    const float* ln2_b  = (const float*)d_in[15];
    const float* W1     = (const float*)d_in[16];
    const float* b1     = (const float*)d_in[17];
    const float* W2     = (const float*)d_in[18];
    const float* b2     = (const float*)d_in[19];
    float* out = (float*)d_out;

    float *y, *q, *k, *v, *g, *attn, *x2, *h, *ff1;
    cudaGetSymbolAddress((void**)&y,    g_y);
    cudaGetSymbolAddress((void**)&q,    g_q);
    cudaGetSymbolAddress((void**)&k,    g_k);
    cudaGetSymbolAddress((void**)&v,    g_v);
    cudaGetSymbolAddress((void**)&g,    g_g);
    cudaGetSymbolAddress((void**)&attn, g_attn);
    cudaGetSymbolAddress((void**)&x2,   g_x2);
    cudaGetSymbolAddress((void**)&h,    g_h);
    cudaGetSymbolAddress((void**)&ff1,  g_ff1);

    dim3 gD(D_MODEL / 128, MROWS / 128);   // 8 x 128
    dim3 gF(DFF / 128,     MROWS / 128);   // 32 x 128

    ln_kernel<<<MROWS, 256>>>(x, ln1_g, ln1_b, y);

    tgemm<0><<<gD, 256>>>(y, Wq, bq, nullptr, q, D_MODEL, D_MODEL);
    tgemm<0><<<gD, 256>>>(y, Wk, bk, nullptr, k, D_MODEL, D_MODEL);
    tgemm<0><<<gD, 256>>>(y, Wv, bv, nullptr, v, D_MODEL, D_MODEL);
    tgemm<1><<<gD, 256>>>(y, Wg, bg, nullptr, g, D_MODEL, D_MODEL);

    scan_partial<<<256, 256>>>(dlogit);
    scan_final  <<<256, 256>>>(dlogit);

    tgemm<2><<<gD, 256>>>(attn, Wo, bo, x, x2, D_MODEL, D_MODEL);

    ln_kernel<<<MROWS, 256>>>(x2, ln2_g, ln2_b, h);

    tgemm<3><<<gF, 256>>>(h,   W1, b1, nullptr, ff1, D_MODEL, DFF);
    tgemm<2><<<gD, 256>>>(ff1, W2, b2, x2,      out, DFF,     D_MODEL);
}

// round 8
// speedup vs baseline: 4.7629x; 1.5912x over previous
#include <cuda_runtime.h>
#include <cuda_fp16.h>
#include <math.h>
#include <stdint.h>

#define D_MODEL 1024
#define NHEADS 16
#define DHEAD 64
#define BATCH 4
#define SEQL 4096
#define MROWS (BATCH*SEQL)      /* 16384 */
#define DFF (4*D_MODEL)         /* 4096  */
#define EPSLN 1e-5f
#define NCHUNK 16
#define CLEN (SEQL/NCHUNK)      /* 256   */

// ---------------- scratch (device globals; no allocation allowed) ----------
__device__ float  g_q   [MROWS*D_MODEL];
__device__ float  g_k   [MROWS*D_MODEL];
__device__ float  g_v   [MROWS*D_MODEL];
__device__ float  g_g   [MROWS*D_MODEL];
__device__ float  g_x2  [MROWS*D_MODEL];
__device__ __half g_y   [MROWS*D_MODEL];
__device__ __half g_attn[MROWS*D_MODEL];
__device__ __half g_h   [MROWS*D_MODEL];
__device__ __half g_ff1 [MROWS*DFF];
__device__ float  g_P   [BATCH*NHEADS*NCHUNK*DHEAD];
// transposed fp16 weights [N,K]
__device__ __half g_wtq [D_MODEL*D_MODEL];
__device__ __half g_wtk [D_MODEL*D_MODEL];
__device__ __half g_wtv [D_MODEL*D_MODEL];
__device__ __half g_wtg [D_MODEL*D_MODEL];
__device__ __half g_wto [D_MODEL*D_MODEL];
__device__ __half g_wt1 [D_MODEL*DFF];
__device__ __half g_wt2 [DFF*D_MODEL];

#define CP16(dst, src) asm volatile( \
    "cp.async.cg.shared.global [%0], [%1], 16;\n" :: "r"(dst), "l"(src))
#define CPCOMMIT() asm volatile("cp.async.commit_group;\n" ::: "memory")
#define CPWAIT0()  asm volatile("cp.async.wait_group 0;\n" ::: "memory")

// ---------------- transpose weights -> fp16 [N,K] ---------------------------
__global__ void transpose_h(const float* __restrict__ W, __half* __restrict__ Wt,
                            int K, int N) {
    __shared__ float t[32][33];
    int n0 = blockIdx.x * 32, k0 = blockIdx.y * 32;
    int tx = threadIdx.x, ty = threadIdx.y;
    t[ty][tx] = W[(size_t)(k0 + ty) * N + n0 + tx];
    __syncthreads();
    Wt[(size_t)(n0 + ty) * K + k0 + tx] = __float2half_rn(t[tx][ty]);
}

// ---------------- LayerNorm: one block per row, out = fp16 ------------------
__global__ void ln_kernel(const float* __restrict__ x,
                          const float* __restrict__ gw,
                          const float* __restrict__ bw,
                          __half* __restrict__ out) {
    int row = blockIdx.x;
    int t = threadIdx.x;                       // 256 threads, 4 elems each
    const float4* xr = (const float4*)(x + (size_t)row * D_MODEL);
    float4 v = xr[t];
    float s  = v.x + v.y + v.z + v.w;
    float ss = v.x*v.x + v.y*v.y + v.z*v.z + v.w*v.w;
    #pragma unroll
    for (int o = 16; o > 0; o >>= 1) {
        s  += __shfl_xor_sync(0xFFFFFFFFu, s,  o);
        ss += __shfl_xor_sync(0xFFFFFFFFu, ss, o);
    }
    __shared__ float red[2][8];
    int warp = t >> 5, lane = t & 31;
    if (lane == 0) { red[0][warp] = s; red[1][warp] = ss; }
    __syncthreads();
    if (t == 0) {
        float a = 0.f, c = 0.f;
        #pragma unroll
        for (int i = 0; i < 8; i++) { a += red[0][i]; c += red[1][i]; }
        float mu  = a * (1.f / D_MODEL);
        float var = c * (1.f / D_MODEL) - mu * mu;
        red[0][0] = mu;
        red[1][0] = rsqrtf(var + EPSLN);
    }
    __syncthreads();
    float mu = red[0][0], rs = red[1][0];
    float4 gv = ((const float4*)gw)[t];
    float4 bv = ((const float4*)bw)[t];
    __half2 h0 = __floats2half2_rn((v.x - mu) * rs * gv.x + bv.x,
                                   (v.y - mu) * rs * gv.y + bv.y);
    __half2 h1 = __floats2half2_rn((v.z - mu) * rs * gv.z + bv.z,
                                   (v.w - mu) * rs * gv.w + bv.w);
    __half2* op = (__half2*)(out + (size_t)row * D_MODEL + t * 4);
    op[0] = h0;
    op[1] = h1;
}

// ---------------- FP16 tensor-core GEMM -------------------------------------
// 128x128 block tile, BK=32, 256 threads (8 warps 2x4), warp tile 64x32,
// mma.sync.m16n8k16.f16 (fp32 accum), 2-stage cp.async double buffer.
// A fp16 [M,K]; Bt fp16 [N,K]; bias fp32; Res fp32.
// EPI: 0 = bias, 1 = bias+sigmoid, 2 = bias+residual, 3 = bias+exact gelu
// OUTH: 1 -> C is fp16, else fp32.
template <int EPI, int OUTH>
__global__ __launch_bounds__(256) void hgemm(
        const __half* __restrict__ A, const __half* __restrict__ Bt,
        const float* __restrict__ bias, const float* __restrict__ Res,
        void* __restrict__ Cv, int K, int N) {
    __shared__ __half As[2][128][40];   // [m][k] pad 32->40 halves (80B rows)
    __shared__ __half Bs[2][128][40];   // [n][k]

    int tid  = threadIdx.x;
    int bm   = blockIdx.y * 128, bn = blockIdx.x * 128;
    int warp = tid >> 5, lane = tid & 31;
    int wm   = (warp >> 2) * 64;        // warp M offset (0/64)
    int wn   = (warp & 3) * 32;         // warp N offset (0/32/64/96)
    int gid  = lane >> 2, ctig = lane & 3;

    int l_row = tid >> 1;               // 0..127
    int l_c   = (tid & 1) * 16;         // half-offset 0 or 16

    float acc[4][4][4];
    #pragma unroll
    for (int i = 0; i < 4; i++)
        #pragma unroll
        for (int j = 0; j < 4; j++)
            #pragma unroll
            for (int r = 0; r < 4; r++) acc[i][j][r] = 0.f;

    const __half* Ag = A  + (size_t)(bm + l_row) * K + l_c;
    const __half* Bg = Bt + (size_t)(bn + l_row) * K + l_c;

    auto load_tile = [&](int t, int buf) {
        int k0 = t * 32;
        uint32_t ad = (uint32_t)__cvta_generic_to_shared(&As[buf][l_row][l_c]);
        const __half* as = Ag + k0;
        CP16(ad, as); CP16(ad + 16, as + 8);
        uint32_t bd = (uint32_t)__cvta_generic_to_shared(&Bs[buf][l_row][l_c]);
        const __half* bs = Bg + k0;
        CP16(bd, bs); CP16(bd + 16, bs + 8);
        CPCOMMIT();
    };

    int T = K >> 5;
    load_tile(0, 0);

    for (int t = 0; t < T; t++) {
        int buf = t & 1;
        CPWAIT0();
        __syncthreads();
        if (t + 1 < T) load_tile(t + 1, buf ^ 1);

        const __half (* __restrict__ Ab)[40] = As[buf];
        const __half (* __restrict__ Bb)[40] = Bs[buf];
        #pragma unroll
        for (int ks = 0; ks < 32; ks += 16) {
            uint32_t af[4][4], bf[4][2];
            #pragma unroll
            for (int im = 0; im < 4; im++) {
                int m0 = wm + im * 16 + gid;
                af[im][0] = *(const uint32_t*)&Ab[m0    ][ks + 2 * ctig];
                af[im][1] = *(const uint32_t*)&Ab[m0 + 8][ks + 2 * ctig];
                af[im][2] = *(const uint32_t*)&Ab[m0    ][ks + 2 * ctig + 8];
                af[im][3] = *(const uint32_t*)&Ab[m0 + 8][ks + 2 * ctig + 8];
            }
            #pragma unroll
            for (int jn = 0; jn < 4; jn++) {
                int n0 = wn + jn * 8 + gid;
                bf[jn][0] = *(const uint32_t*)&Bb[n0][ks + 2 * ctig];
                bf[jn][1] = *(const uint32_t*)&Bb[n0][ks + 2 * ctig + 8];
            }
            #pragma unroll
            for (int im = 0; im < 4; im++)
                #pragma unroll
                for (int jn = 0; jn < 4; jn++) {
                    asm volatile(
                        "mma.sync.aligned.m16n8k16.row.col.f32.f16.f16.f32 "
                        "{%0,%1,%2,%3}, {%4,%5,%6,%7}, {%8,%9}, {%0,%1,%2,%3};\n"
                        : "+f"(acc[im][jn][0]), "+f"(acc[im][jn][1]),
                          "+f"(acc[im][jn][2]), "+f"(acc[im][jn][3])
                        : "r"(af[im][0]), "r"(af[im][1]),
                          "r"(af[im][2]), "r"(af[im][3]),
                          "r"(bf[jn][0]), "r"(bf[jn][1]));
                }
        }
        __syncthreads();
    }

    // epilogue
    float* Cf = (float*)Cv;
    __half* Ch = (__half*)Cv;
    #pragma unroll
    for (int im = 0; im < 4; im++) {
        #pragma unroll
        for (int jn = 0; jn < 4; jn++) {
            int m = bm + wm + im * 16 + gid;
            int n = bn + wn + jn * 8 + ctig * 2;
            float2 bb = *(const float2*)(bias + n);
            float v0 = acc[im][jn][0] + bb.x;
            float v1 = acc[im][jn][1] + bb.y;
            float v2 = acc[im][jn][2] + bb.x;
            float v3 = acc[im][jn][3] + bb.y;
            if (EPI == 1) {
                v0 = 1.f / (1.f + expf(-v0));
                v1 = 1.f / (1.f + expf(-v1));
                v2 = 1.f / (1.f + expf(-v2));
                v3 = 1.f / (1.f + expf(-v3));
            } else if (EPI == 2) {
                float2 r0 = *(const float2*)(Res + (size_t)m * N + n);
                float2 r1 = *(const float2*)(Res + (size_t)(m + 8) * N + n);
                v0 += r0.x; v1 += r0.y; v2 += r1.x; v3 += r1.y;
            } else if (EPI == 3) {
                const float c = 0.70710678118654752f;
                v0 = 0.5f * v0 * (1.f + erff(v0 * c));
                v1 = 0.5f * v1 * (1.f + erff(v1 * c));
                v2 = 0.5f * v2 * (1.f + erff(v2 * c));
                v3 = 0.5f * v3 * (1.f + erff(v3 * c));
            }
            if (OUTH) {
                __half2 h0 = __floats2half2_rn(v0, v1);
                __half2 h1 = __floats2half2_rn(v2, v3);
                *(__half2*)(Ch + (size_t)m * N + n)       = h0;
                *(__half2*)(Ch + (size_t)(m + 8) * N + n) = h1;
            } else {
                *(float2*)(Cf + (size_t)m * N + n)       = make_float2(v0, v1);
                *(float2*)(Cf + (size_t)(m + 8) * N + n) = make_float2(v2, v3);
            }
        }
    }
}

// ---------------- Retention scan (chunked associative scan) ---------------
__device__ __forceinline__ void unit_decompose(int tid, int bx,
                                               int& b, int& h, int& chunk, int& d) {
    d = tid & 63;
    int unit = bx * 4 + (tid >> 6);
    chunk = unit & (NCHUNK - 1);
    int bh = unit >> 4;
    h = bh & (NHEADS - 1);
    b = bh >> 4;
}

__global__ void scan_partial(const float* __restrict__ dlogit) {
    int b, h, chunk, d;
    unit_decompose(threadIdx.x, blockIdx.x, b, h, chunk, d);
    float decay = 1.f / (1.f + expf(-dlogit[h]));
    float p = 0.f;
    size_t base = ((size_t)(b * SEQL + chunk * CLEN)) * D_MODEL + h * DHEAD + d;
    #pragma unroll 4
    for (int i = 0; i < CLEN; i++) {
        size_t idx = base + (size_t)i * D_MODEL;
        p = decay * p + g_k[idx] * g_v[idx];
    }
    int bh = b * NHEADS + h;
    g_P[(bh * NCHUNK + chunk) * DHEAD + d] = p;
}

__global__ void scan_final(const float* __restrict__ dlogit) {
    int b, h, chunk, d;
    unit_decompose(threadIdx.x, blockIdx.x, b, h, chunk, d);
    float decay = 1.f / (1.f + expf(-dlogit[h]));
    float dCL = powf(decay, (float)CLEN);
    int bh = b * NHEADS + h;
    float s = 0.f;
    for (int j = 0; j < chunk; j++)
        s = dCL * s + g_P[(bh * NCHUNK + j) * DHEAD + d];
    const float scale = 0.125f;   // DHEAD^-0.5
    size_t base = ((size_t)(b * SEQL + chunk * CLEN)) * D_MODEL + h * DHEAD + d;
    #pragma unroll 4
    for (int i = 0; i < CLEN; i++) {
        size_t idx = base + (size_t)i * D_MODEL;
        s = decay * s + g_k[idx] * g_v[idx];
        g_attn[idx] = __float2half_rn(g_g[idx] * g_q[idx] * s * scale);
    }
}

// ---------------- launch ---------------------------------------------------
extern "C" void kernel_launch(void* const* d_in, const int* in_sizes, int n_in,
                              void* d_out, int out_size) {
    const float* x      = (const float*)d_in[0];
    const float* ln1_g  = (const float*)d_in[1];
    const float* ln1_b  = (const float*)d_in[2];
    const float* Wq     = (const float*)d_in[3];
    const float* bq     = (const float*)d_in[4];
    const float* Wk     = (const float*)d_in[5];
    const float* bk     = (const float*)d_in[6];
    const float* Wv     = (const float*)d_in[7];
    const float* bv     = (const float*)d_in[8];
    const float* Wg     = (const float*)d_in[9];
    const float* bg     = (const float*)d_in[10];
    const float* dlogit = (const float*)d_in[11];
    const float* Wo     = (const float*)d_in[12];
    const float* bo     = (const float*)d_in[13];
    const float* ln2_g  = (const float*)d_in[14];
    const float* ln2_b  = (const float*)d_in[15];
    const float* W1     = (const float*)d_in[16];
    const float* b1     = (const float*)d_in[17];
    const float* W2     = (const float*)d_in[18];
    const float* b2     = (const float*)d_in[19];
    float* out = (float*)d_out;

    float  *q, *k, *v, *g, *x2;
    __half *y, *attn, *h, *ff1;
    __half *wtq, *wtk, *wtv, *wtg, *wto, *wt1, *wt2;
    cudaGetSymbolAddress((void**)&q,    g_q);
    cudaGetSymbolAddress((void**)&k,    g_k);
    cudaGetSymbolAddress((void**)&v,    g_v);
    cudaGetSymbolAddress((void**)&g,    g_g);
    cudaGetSymbolAddress((void**)&x2,   g_x2);
    cudaGetSymbolAddress((void**)&y,    g_y);
    cudaGetSymbolAddress((void**)&attn, g_attn);
    cudaGetSymbolAddress((void**)&h,    g_h);
    cudaGetSymbolAddress((void**)&ff1,  g_ff1);
    cudaGetSymbolAddress((void**)&wtq,  g_wtq);
    cudaGetSymbolAddress((void**)&wtk,  g_wtk);
    cudaGetSymbolAddress((void**)&wtv,  g_wtv);
    cudaGetSymbolAddress((void**)&wtg,  g_wtg);
    cudaGetSymbolAddress((void**)&wto,  g_wto);
    cudaGetSymbolAddress((void**)&wt1,  g_wt1);
    cudaGetSymbolAddress((void**)&wt2,  g_wt2);

    dim3 tb(32, 32);
    transpose_h<<<dim3(D_MODEL/32, D_MODEL/32), tb>>>(Wq, wtq, D_MODEL, D_MODEL);
    transpose_h<<<dim3(D_MODEL/32, D_MODEL/32), tb>>>(Wk, wtk, D_MODEL, D_MODEL);
    transpose_h<<<dim3(D_MODEL/32, D_MODEL/32), tb>>>(Wv, wtv, D_MODEL, D_MODEL);
    transpose_h<<<dim3(D_MODEL/32, D_MODEL/32), tb>>>(Wg, wtg, D_MODEL, D_MODEL);
    transpose_h<<<dim3(D_MODEL/32, D_MODEL/32), tb>>>(Wo, wto, D_MODEL, D_MODEL);
    transpose_h<<<dim3(DFF/32,     D_MODEL/32), tb>>>(W1, wt1, D_MODEL, DFF);
    transpose_h<<<dim3(D_MODEL/32, DFF/32),     tb>>>(W2, wt2, DFF, D_MODEL);

    dim3 gD(D_MODEL / 128, MROWS / 128);   // 8 x 128
    dim3 gF(DFF / 128,     MROWS / 128);   // 32 x 128

    ln_kernel<<<MROWS, 256>>>(x, ln1_g, ln1_b, y);

    hgemm<0,0><<<gD, 256>>>(y, wtq, bq, nullptr, q, D_MODEL, D_MODEL);
    hgemm<0,0><<<gD, 256>>>(y, wtk, bk, nullptr, k, D_MODEL, D_MODEL);
    hgemm<0,0><<<gD, 256>>>(y, wtv, bv, nullptr, v, D_MODEL, D_MODEL);
    hgemm<1,0><<<gD, 256>>>(y, wtg, bg, nullptr, g, D_MODEL, D_MODEL);

    scan_partial<<<256, 256>>>(dlogit);
    scan_final  <<<256, 256>>>(dlogit);

    hgemm<2,0><<<gD, 256>>>(attn, wto, bo, x, x2, D_MODEL, D_MODEL);

    ln_kernel<<<MROWS, 256>>>(x2, ln2_g, ln2_b, h);

    hgemm<3,1><<<gF, 256>>>(h,   wt1, b1, nullptr, ff1, D_MODEL, DFF);
    hgemm<2,0><<<gD, 256>>>(ff1, wt2, b2, x2,      out, DFF,     D_MODEL);
}

// round 9
// speedup vs baseline: 4.8731x; 1.0231x over previous
#include <cuda_runtime.h>
#include <cuda_fp16.h>
#include <math.h>
#include <stdint.h>

#define D_MODEL 1024
#define NHEADS 16
#define DHEAD 64
#define BATCH 4
#define SEQL 4096
#define MROWS (BATCH*SEQL)      /* 16384 */
#define DFF (4*D_MODEL)         /* 4096  */
#define QKVG_N (4*D_MODEL)      /* 4096  */
#define EPSLN 1e-5f
#define NCHUNK 16
#define CLEN (SEQL/NCHUNK)      /* 256   */

// ---------------- scratch (device globals; no allocation allowed) ----------
__device__ __half g_qkvg[(size_t)MROWS*QKVG_N];  // cols: [q | k | v | g]
__device__ float  g_x2  [MROWS*D_MODEL];
__device__ __half g_y   [MROWS*D_MODEL];
__device__ __half g_attn[MROWS*D_MODEL];
__device__ __half g_h   [MROWS*D_MODEL];
__device__ __half g_ff1 [(size_t)MROWS*DFF];
__device__ float  g_P   [BATCH*NHEADS*NCHUNK*DHEAD];
__device__ float  g_bqkvg[QKVG_N];
// transposed fp16 weights [N,K]
__device__ __half g_wtqkvg[(size_t)QKVG_N*D_MODEL];
__device__ __half g_wto [D_MODEL*D_MODEL];
__device__ __half g_wt1 [(size_t)D_MODEL*DFF];
__device__ __half g_wt2 [(size_t)DFF*D_MODEL];

#define CP16(dst, src) asm volatile( \
    "cp.async.cg.shared.global [%0], [%1], 16;\n" :: "r"(dst), "l"(src))
#define CPCOMMIT() asm volatile("cp.async.commit_group;\n" ::: "memory")
#define CPWAIT0()  asm volatile("cp.async.wait_group 0;\n" ::: "memory")
#define LDSM4(r0, r1, r2, r3, addr) asm volatile( \
    "ldmatrix.sync.aligned.m8n8.x4.shared.b16 {%0,%1,%2,%3}, [%4];" \
    : "=r"(r0), "=r"(r1), "=r"(r2), "=r"(r3) : "r"(addr))

// ---------------- transpose weights -> fp16 [N,K] ---------------------------
__global__ void transpose_h(const float* __restrict__ W, __half* __restrict__ Wt,
                            int K, int N) {
    __shared__ float t[32][33];
    int n0 = blockIdx.x * 32, k0 = blockIdx.y * 32;
    int tx = threadIdx.x, ty = threadIdx.y;
    t[ty][tx] = W[(size_t)(k0 + ty) * N + n0 + tx];
    __syncthreads();
    Wt[(size_t)(n0 + ty) * K + k0 + tx] = __float2half_rn(t[tx][ty]);
}

__global__ void pack_bias(const float* __restrict__ bq, const float* __restrict__ bk,
                          const float* __restrict__ bv, const float* __restrict__ bg,
                          float* __restrict__ o) {
    int i = blockIdx.x * 256 + threadIdx.x;
    float r;
    if      (i < 1024) r = bq[i];
    else if (i < 2048) r = bk[i - 1024];
    else if (i < 3072) r = bv[i - 2048];
    else               r = bg[i - 3072];
    o[i] = r;
}

// ---------------- LayerNorm: one block per row, out = fp16 ------------------
__global__ void ln_kernel(const float* __restrict__ x,
                          const float* __restrict__ gw,
                          const float* __restrict__ bw,
                          __half* __restrict__ out) {
    int row = blockIdx.x;
    int t = threadIdx.x;
    const float4* xr = (const float4*)(x + (size_t)row * D_MODEL);
    float4 v = xr[t];
    float s  = v.x + v.y + v.z + v.w;
    float ss = v.x*v.x + v.y*v.y + v.z*v.z + v.w*v.w;
    #pragma unroll
    for (int o = 16; o > 0; o >>= 1) {
        s  += __shfl_xor_sync(0xFFFFFFFFu, s,  o);
        ss += __shfl_xor_sync(0xFFFFFFFFu, ss, o);
    }
    __shared__ float red[2][8];
    int warp = t >> 5, lane = t & 31;
    if (lane == 0) { red[0][warp] = s; red[1][warp] = ss; }
    __syncthreads();
    if (t == 0) {
        float a = 0.f, c = 0.f;
        #pragma unroll
        for (int i = 0; i < 8; i++) { a += red[0][i]; c += red[1][i]; }
        float mu  = a * (1.f / D_MODEL);
        float var = c * (1.f / D_MODEL) - mu * mu;
        red[0][0] = mu;
        red[1][0] = rsqrtf(var + EPSLN);
    }
    __syncthreads();
    float mu = red[0][0], rs = red[1][0];
    float4 gv = ((const float4*)gw)[t];
    float4 bv = ((const float4*)bw)[t];
    __half2 h0 = __floats2half2_rn((v.x - mu) * rs * gv.x + bv.x,
                                   (v.y - mu) * rs * gv.y + bv.y);
    __half2 h1 = __floats2half2_rn((v.z - mu) * rs * gv.z + bv.z,
                                   (v.w - mu) * rs * gv.w + bv.w);
    __half2* op = (__half2*)(out + (size_t)row * D_MODEL + t * 4);
    op[0] = h0;
    op[1] = h1;
}

// ---------------- FP16 tensor-core GEMM -------------------------------------
// 128x128 block tile, BK=32, 256 threads (8 warps 2x4), warp tile 64x32,
// mma.sync.m16n8k16.f16 fp32-acc, ldmatrix fragments, cp.async double buffer.
// EPI: 0 bias, 1 bias+sigmoid, 2 bias+residual, 3 bias+gelu,
//      4 bias + sigmoid only for n >= 3*D_MODEL (fused QKVG epilogue)
// OUTH: 1 -> C fp16, else fp32.
template <int EPI, int OUTH>
__global__ __launch_bounds__(256) void hgemm(
        const __half* __restrict__ A, const __half* __restrict__ Bt,
        const float* __restrict__ bias, const float* __restrict__ Res,
        void* __restrict__ Cv, int K, int N) {
    __shared__ __half As[2][128][40];   // 80B rows
    __shared__ __half Bs[2][128][40];

    int tid  = threadIdx.x;
    int bm   = blockIdx.y * 128, bn = blockIdx.x * 128;
    int warp = tid >> 5, lane = tid & 31;
    int wm   = (warp >> 2) * 64;
    int wn   = (warp & 3) * 32;
    int gid  = lane >> 2, ctig = lane & 3;
    int lrow = lane & 15, lsel = (lane >> 4) * 8;   // ldmatrix lane mapping

    int l_row = tid >> 1;
    int l_c   = (tid & 1) * 16;

    float acc[4][4][4];
    #pragma unroll
    for (int i = 0; i < 4; i++)
        #pragma unroll
        for (int j = 0; j < 4; j++)
            #pragma unroll
            for (int r = 0; r < 4; r++) acc[i][j][r] = 0.f;

    const __half* Ag = A  + (size_t)(bm + l_row) * K + l_c;
    const __half* Bg = Bt + (size_t)(bn + l_row) * K + l_c;

    auto load_tile = [&](int t, int buf) {
        int k0 = t * 32;
        uint32_t ad = (uint32_t)__cvta_generic_to_shared(&As[buf][l_row][l_c]);
        const __half* as = Ag + k0;
        CP16(ad, as); CP16(ad + 16, as + 8);
        uint32_t bd = (uint32_t)__cvta_generic_to_shared(&Bs[buf][l_row][l_c]);
        const __half* bs = Bg + k0;
        CP16(bd, bs); CP16(bd + 16, bs + 8);
        CPCOMMIT();
    };

    int T = K >> 5;
    load_tile(0, 0);

    for (int t = 0; t < T; t++) {
        int buf = t & 1;
        CPWAIT0();
        __syncthreads();
        if (t + 1 < T) load_tile(t + 1, buf ^ 1);

        uint32_t a_base = (uint32_t)__cvta_generic_to_shared(
            &As[buf][wm + lrow][lsel]);
        uint32_t b_base = (uint32_t)__cvta_generic_to_shared(
            &Bs[buf][wn + lrow][lsel]);

        #pragma unroll
        for (int ks = 0; ks < 32; ks += 16) {
            uint32_t af[4][4], bf[4][2];
            #pragma unroll
            for (int im = 0; im < 4; im++)
                LDSM4(af[im][0], af[im][1], af[im][2], af[im][3],
                      a_base + im * 1280 + ks * 2);
            #pragma unroll
            for (int p = 0; p < 2; p++) {
                uint32_t r0, r1, r2, r3;
                LDSM4(r0, r1, r2, r3, b_base + p * 1280 + ks * 2);
                bf[2*p    ][0] = r0; bf[2*p + 1][0] = r1;
                bf[2*p    ][1] = r2; bf[2*p + 1][1] = r3;
            }
            #pragma unroll
            for (int im = 0; im < 4; im++)
                #pragma unroll
                for (int jn = 0; jn < 4; jn++) {
                    asm volatile(
                        "mma.sync.aligned.m16n8k16.row.col.f32.f16.f16.f32 "
                        "{%0,%1,%2,%3}, {%4,%5,%6,%7}, {%8,%9}, {%0,%1,%2,%3};\n"
                        : "+f"(acc[im][jn][0]), "+f"(acc[im][jn][1]),
                          "+f"(acc[im][jn][2]), "+f"(acc[im][jn][3])
                        : "r"(af[im][0]), "r"(af[im][1]),
                          "r"(af[im][2]), "r"(af[im][3]),
                          "r"(bf[jn][0]), "r"(bf[jn][1]));
                }
        }
        __syncthreads();
    }

    // epilogue
    float* Cf = (float*)Cv;
    __half* Ch = (__half*)Cv;
    #pragma unroll
    for (int im = 0; im < 4; im++) {
        #pragma unroll
        for (int jn = 0; jn < 4; jn++) {
            int m = bm + wm + im * 16 + gid;
            int n = bn + wn + jn * 8 + ctig * 2;
            float2 bb = *(const float2*)(bias + n);
            float v0 = acc[im][jn][0] + bb.x;
            float v1 = acc[im][jn][1] + bb.y;
            float v2 = acc[im][jn][2] + bb.x;
            float v3 = acc[im][jn][3] + bb.y;
            if (EPI == 1 || (EPI == 4 && n >= 3 * D_MODEL)) {
                v0 = 1.f / (1.f + expf(-v0));
                v1 = 1.f / (1.f + expf(-v1));
                v2 = 1.f / (1.f + expf(-v2));
                v3 = 1.f / (1.f + expf(-v3));
            } else if (EPI == 2) {
                float2 r0 = *(const float2*)(Res + (size_t)m * N + n);
                float2 r1 = *(const float2*)(Res + (size_t)(m + 8) * N + n);
                v0 += r0.x; v1 += r0.y; v2 += r1.x; v3 += r1.y;
            } else if (EPI == 3) {
                const float c = 0.70710678118654752f;
                v0 = 0.5f * v0 * (1.f + erff(v0 * c));
                v1 = 0.5f * v1 * (1.f + erff(v1 * c));
                v2 = 0.5f * v2 * (1.f + erff(v2 * c));
                v3 = 0.5f * v3 * (1.f + erff(v3 * c));
            }
            if (OUTH) {
                *(__half2*)(Ch + (size_t)m * N + n)       = __floats2half2_rn(v0, v1);
                *(__half2*)(Ch + (size_t)(m + 8) * N + n) = __floats2half2_rn(v2, v3);
            } else {
                *(float2*)(Cf + (size_t)m * N + n)       = make_float2(v0, v1);
                *(float2*)(Cf + (size_t)(m + 8) * N + n) = make_float2(v2, v3);
            }
        }
    }
}

// ---------------- Retention scan (chunked associative scan) ---------------
// qkvg layout: row-major [MROWS][4096], cols [q | k | v | g]
__device__ __forceinline__ void unit_decompose(int tid, int bx,
                                               int& b, int& h, int& chunk, int& d) {
    d = tid & 63;
    int unit = bx * 4 + (tid >> 6);
    chunk = unit & (NCHUNK - 1);
    int bh = unit >> 4;
    h = bh & (NHEADS - 1);
    b = bh >> 4;
}

__global__ void scan_partial(const float* __restrict__ dlogit) {
    int b, h, chunk, d;
    unit_decompose(threadIdx.x, blockIdx.x, b, h, chunk, d);
    float decay = 1.f / (1.f + expf(-dlogit[h]));
    float p = 0.f;
    size_t base = ((size_t)(b * SEQL + chunk * CLEN)) * QKVG_N + h * DHEAD + d;
    const __half* kp = g_qkvg + base + D_MODEL;
    const __half* vp = g_qkvg + base + 2 * D_MODEL;
    #pragma unroll 4
    for (int i = 0; i < CLEN; i++) {
        size_t o = (size_t)i * QKVG_N;
        p = decay * p + __half2float(kp[o]) * __half2float(vp[o]);
    }
    int bh = b * NHEADS + h;
    g_P[(bh * NCHUNK + chunk) * DHEAD + d] = p;
}

__global__ void scan_final(const float* __restrict__ dlogit) {
    int b, h, chunk, d;
    unit_decompose(threadIdx.x, blockIdx.x, b, h, chunk, d);
    float decay = 1.f / (1.f + expf(-dlogit[h]));
    float dCL = powf(decay, (float)CLEN);
    int bh = b * NHEADS + h;
    float s = 0.f;
    for (int j = 0; j < chunk; j++)
        s = dCL * s + g_P[(bh * NCHUNK + j) * DHEAD + d];
    const float scale = 0.125f;   // DHEAD^-0.5
    int row0 = b * SEQL + chunk * CLEN;
    size_t base = (size_t)row0 * QKVG_N + h * DHEAD + d;
    const __half* qp = g_qkvg + base;
    const __half* kp = g_qkvg + base + D_MODEL;
    const __half* vp = g_qkvg + base + 2 * D_MODEL;
    const __half* gp = g_qkvg + base + 3 * D_MODEL;
    __half* ap = g_attn + (size_t)row0 * D_MODEL + h * DHEAD + d;
    #pragma unroll 4
    for (int i = 0; i < CLEN; i++) {
        size_t o = (size_t)i * QKVG_N;
        s = decay * s + __half2float(kp[o]) * __half2float(vp[o]);
        float r = __half2float(gp[o]) * __half2float(qp[o]) * s * scale;
        ap[(size_t)i * D_MODEL] = __float2half_rn(r);
    }
}

// ---------------- launch ---------------------------------------------------
extern "C" void kernel_launch(void* const* d_in, const int* in_sizes, int n_in,
                              void* d_out, int out_size) {
    const float* x      = (const float*)d_in[0];
    const float* ln1_g  = (const float*)d_in[1];
    const float* ln1_b  = (const float*)d_in[2];
    const float* Wq     = (const float*)d_in[3];
    const float* bq     = (const float*)d_in[4];
    const float* Wk     = (const float*)d_in[5];
    const float* bk     = (const float*)d_in[6];
    const float* Wv     = (const float*)d_in[7];
    const float* bv     = (const float*)d_in[8];
    const float* Wg     = (const float*)d_in[9];
    const float* bg     = (const float*)d_in[10];
    const float* dlogit = (const float*)d_in[11];
    const float* Wo     = (const float*)d_in[12];
    const float* bo     = (const float*)d_in[13];
    const float* ln2_g  = (const float*)d_in[14];
    const float* ln2_b  = (const float*)d_in[15];
    const float* W1     = (const float*)d_in[16];
    const float* b1     = (const float*)d_in[17];
    const float* W2     = (const float*)d_in[18];
    const float* b2     = (const float*)d_in[19];
    float* out = (float*)d_out;

    float  *x2, *bqkvg;
    __half *y, *attn, *h, *ff1, *qkvg;
    __half *wtqkvg, *wto, *wt1, *wt2;
    cudaGetSymbolAddress((void**)&qkvg,   g_qkvg);
    cudaGetSymbolAddress((void**)&x2,     g_x2);
    cudaGetSymbolAddress((void**)&y,      g_y);
    cudaGetSymbolAddress((void**)&attn,   g_attn);
    cudaGetSymbolAddress((void**)&h,      g_h);
    cudaGetSymbolAddress((void**)&ff1,    g_ff1);
    cudaGetSymbolAddress((void**)&bqkvg,  g_bqkvg);
    cudaGetSymbolAddress((void**)&wtqkvg, g_wtqkvg);
    cudaGetSymbolAddress((void**)&wto,    g_wto);
    cudaGetSymbolAddress((void**)&wt1,    g_wt1);
    cudaGetSymbolAddress((void**)&wt2,    g_wt2);

    dim3 tb(32, 32);
    transpose_h<<<dim3(D_MODEL/32, D_MODEL/32), tb>>>(Wq, wtqkvg,                       D_MODEL, D_MODEL);
    transpose_h<<<dim3(D_MODEL/32, D_MODEL/32), tb>>>(Wk, wtqkvg + 1*D_MODEL*D_MODEL,   D_MODEL, D_MODEL);
    transpose_h<<<dim3(D_MODEL/32, D_MODEL/32), tb>>>(Wv, wtqkvg + 2*D_MODEL*D_MODEL,   D_MODEL, D_MODEL);
    transpose_h<<<dim3(D_MODEL/32, D_MODEL/32), tb>>>(Wg, wtqkvg + 3*D_MODEL*D_MODEL,   D_MODEL, D_MODEL);
    transpose_h<<<dim3(D_MODEL/32, D_MODEL/32), tb>>>(Wo, wto, D_MODEL, D_MODEL);
    transpose_h<<<dim3(DFF/32,     D_MODEL/32), tb>>>(W1, wt1, D_MODEL, DFF);
    transpose_h<<<dim3(D_MODEL/32, DFF/32),     tb>>>(W2, wt2, DFF, D_MODEL);
    pack_bias<<<QKVG_N/256, 256>>>(bq, bk, bv, bg, bqkvg);

    dim3 gQ(QKVG_N / 128, MROWS / 128);   // 32 x 128
    dim3 gD(D_MODEL / 128, MROWS / 128);  //  8 x 128
    dim3 gF(DFF / 128,     MROWS / 128);  // 32 x 128

    ln_kernel<<<MROWS, 256>>>(x, ln1_g, ln1_b, y);

    hgemm<4,1><<<gQ, 256>>>(y, wtqkvg, bqkvg, nullptr, qkvg, D_MODEL, QKVG_N);

    scan_partial<<<256, 256>>>(dlogit);
    scan_final  <<<256, 256>>>(dlogit);

    hgemm<2,0><<<gD, 256>>>(attn, wto, bo, x, x2, D_MODEL, D_MODEL);

    ln_kernel<<<MROWS, 256>>>(x2, ln2_g, ln2_b, h);

    hgemm<3,1><<<gF, 256>>>(h,   wt1, b1, nullptr, ff1, D_MODEL, DFF);
    hgemm<2,0><<<gD, 256>>>(ff1, wt2, b2, x2,      out, DFF,     D_MODEL);
}

// round 11
// speedup vs baseline: 5.0162x; 1.0294x over previous
#include <cuda_runtime.h>
#include <cuda_fp16.h>
#include <math.h>
#include <stdint.h>

#define D_MODEL 1024
#define NHEADS 16
#define DHEAD 64
#define BATCH 4
#define SEQL 4096
#define MROWS (BATCH*SEQL)      /* 16384 */
#define DFF (4*D_MODEL)         /* 4096  */
#define QKVG_N (4*D_MODEL)      /* 4096  */
#define EPSLN 1e-5f
#define NCHUNK 16
#define CLEN (SEQL/NCHUNK)      /* 256   */

// ---------------- scratch (device globals; no allocation allowed) ----------
__device__ __half g_qkvg[(size_t)MROWS*QKVG_N];  // cols: [q | k | v | g]
__device__ float  g_x2  [MROWS*D_MODEL];
__device__ __half g_y   [MROWS*D_MODEL];
__device__ __half g_attn[MROWS*D_MODEL];
__device__ __half g_h   [MROWS*D_MODEL];
__device__ __half g_ff1 [(size_t)MROWS*DFF];
__device__ float  g_P   [BATCH*NHEADS*NCHUNK*DHEAD];
__device__ float  g_bqkvg[QKVG_N];
// transposed fp16 weights [N,K]
__device__ __half g_wtqkvg[(size_t)QKVG_N*D_MODEL];
__device__ __half g_wto [D_MODEL*D_MODEL];
__device__ __half g_wt1 [(size_t)D_MODEL*DFF];
__device__ __half g_wt2 [(size_t)DFF*D_MODEL];

#define CP16(dst, src) asm volatile( \
    "cp.async.cg.shared.global [%0], [%1], 16;\n" :: "r"(dst), "l"(src))
#define CPCOMMIT() asm volatile("cp.async.commit_group;\n" ::: "memory")
#define CPWAIT0()  asm volatile("cp.async.wait_group 0;\n" ::: "memory")
#define LDSM4(r0, r1, r2, r3, addr) asm volatile( \
    "ldmatrix.sync.aligned.m8n8.x4.shared.b16 {%0,%1,%2,%3}, [%4];" \
    : "=r"(r0), "=r"(r1), "=r"(r2), "=r"(r3) : "r"(addr))

// ---------------- all weight transposes in ONE launch -----------------------
// tiles: [0,4096) QKVG (4x 1024), [4096,5120) Wo, [5120,9216) W1, [9216,13312) W2
__global__ void transpose_all(const float* __restrict__ Wq, const float* __restrict__ Wk,
                              const float* __restrict__ Wv, const float* __restrict__ Wg,
                              const float* __restrict__ Wo, const float* __restrict__ W1,
                              const float* __restrict__ W2) {
    __shared__ float t[32][33];
    int id = blockIdx.x;
    const float* W; __half* Wt; int K, N, bx, by;
    __half *wtqkvg = g_wtqkvg, *wto = g_wto, *wt1 = g_wt1, *wt2 = g_wt2;
    if (id < 4096) {
        int seg = id >> 10, r = id & 1023;
        const float* srcs[4] = {Wq, Wk, Wv, Wg};
        W = srcs[seg];
        Wt = wtqkvg + (size_t)seg * D_MODEL * D_MODEL;
        K = D_MODEL; N = D_MODEL; bx = r & 31; by = r >> 5;
    } else if (id < 5120) {
        int r = id - 4096;
        W = Wo; Wt = wto; K = D_MODEL; N = D_MODEL; bx = r & 31; by = r >> 5;
    } else if (id < 9216) {
        int r = id - 5120;
        W = W1; Wt = wt1; K = D_MODEL; N = DFF; bx = r & 127; by = r >> 7;
    } else {
        int r = id - 9216;
        W = W2; Wt = wt2; K = DFF; N = D_MODEL; bx = r & 31; by = r >> 5;
    }
    int n0 = bx * 32, k0 = by * 32;
    int tx = threadIdx.x, ty = threadIdx.y;
    t[ty][tx] = W[(size_t)(k0 + ty) * N + n0 + tx];
    __syncthreads();
    Wt[(size_t)(n0 + ty) * K + k0 + tx] = __float2half_rn(t[tx][ty]);
}

__global__ void pack_bias(const float* __restrict__ bq, const float* __restrict__ bk,
                          const float* __restrict__ bv, const float* __restrict__ bg,
                          float* __restrict__ o) {
    int i = blockIdx.x * 256 + threadIdx.x;
    float r;
    if      (i < 1024) r = bq[i];
    else if (i < 2048) r = bk[i - 1024];
    else if (i < 3072) r = bv[i - 2048];
    else               r = bg[i - 3072];
    o[i] = r;
}

// ---------------- LayerNorm: one block per row, out = fp16 ------------------
__global__ void ln_kernel(const float* __restrict__ x,
                          const float* __restrict__ gw,
                          const float* __restrict__ bw,
                          __half* __restrict__ out) {
    int row = blockIdx.x;
    int t = threadIdx.x;
    const float4* xr = (const float4*)(x + (size_t)row * D_MODEL);
    float4 v = xr[t];
    float s  = v.x + v.y + v.z + v.w;
    float ss = v.x*v.x + v.y*v.y + v.z*v.z + v.w*v.w;
    #pragma unroll
    for (int o = 16; o > 0; o >>= 1) {
        s  += __shfl_xor_sync(0xFFFFFFFFu, s,  o);
        ss += __shfl_xor_sync(0xFFFFFFFFu, ss, o);
    }
    __shared__ float red[2][8];
    int warp = t >> 5, lane = t & 31;
    if (lane == 0) { red[0][warp] = s; red[1][warp] = ss; }
    __syncthreads();
    if (t == 0) {
        float a = 0.f, c = 0.f;
        #pragma unroll
        for (int i = 0; i < 8; i++) { a += red[0][i]; c += red[1][i]; }
        float mu  = a * (1.f / D_MODEL);
        float var = c * (1.f / D_MODEL) - mu * mu;
        red[0][0] = mu;
        red[1][0] = rsqrtf(var + EPSLN);
    }
    __syncthreads();
    float mu = red[0][0], rs = red[1][0];
    float4 gv = ((const float4*)gw)[t];
    float4 bv = ((const float4*)bw)[t];
    __half2 h0 = __floats2half2_rn((v.x - mu) * rs * gv.x + bv.x,
                                   (v.y - mu) * rs * gv.y + bv.y);
    __half2 h1 = __floats2half2_rn((v.z - mu) * rs * gv.z + bv.z,
                                   (v.w - mu) * rs * gv.w + bv.w);
    __half2* op = (__half2*)(out + (size_t)row * D_MODEL + t * 4);
    op[0] = h0;
    op[1] = h1;
}

// ---------------- FP16 tensor-core GEMM -------------------------------------
// 128x128 block tile, BK=32, 256 threads (8 warps 2x4), warp tile 64x32,
// mma.sync.m16n8k16.f16 fp32-acc, ldmatrix fragments, cp.async double buffer.
// __launch_bounds__(256,2): force regs<=128 so 2 CTAs co-reside per SM.
// EPI: 0 bias, 1 bias+sigmoid, 2 bias+residual, 3 bias+gelu,
//      4 bias + sigmoid only for n >= 3*D_MODEL (fused QKVG epilogue)
// OUTH: 1 -> C fp16, else fp32.
template <int EPI, int OUTH>
__global__ __launch_bounds__(256, 2) void hgemm(
        const __half* __restrict__ A, const __half* __restrict__ Bt,
        const float* __restrict__ bias, const float* __restrict__ Res,
        void* __restrict__ Cv, int K, int N) {
    __shared__ __half As[2][128][40];   // 80B rows
    __shared__ __half Bs[2][128][40];

    int tid  = threadIdx.x;
    int bm   = blockIdx.y * 128, bn = blockIdx.x * 128;
    int warp = tid >> 5, lane = tid & 31;
    int wm   = (warp >> 2) * 64;
    int wn   = (warp & 3) * 32;
    int gid  = lane >> 2, ctig = lane & 3;
    int lrow = lane & 15, lsel = (lane >> 4) * 8;   // ldmatrix lane mapping

    int l_row = tid >> 1;
    int l_c   = (tid & 1) * 16;

    float acc[4][4][4];
    #pragma unroll
    for (int i = 0; i < 4; i++)
        #pragma unroll
        for (int j = 0; j < 4; j++)
            #pragma unroll
            for (int r = 0; r < 4; r++) acc[i][j][r] = 0.f;

    const __half* Ag = A  + (size_t)(bm + l_row) * K + l_c;
    const __half* Bg = Bt + (size_t)(bn + l_row) * K + l_c;

    auto load_tile = [&](int t, int buf) {
        int k0 = t * 32;
        uint32_t ad = (uint32_t)__cvta_generic_to_shared(&As[buf][l_row][l_c]);
        const __half* as = Ag + k0;
        CP16(ad, as); CP16(ad + 16, as + 8);
        uint32_t bd = (uint32_t)__cvta_generic_to_shared(&Bs[buf][l_row][l_c]);
        const __half* bs = Bg + k0;
        CP16(bd, bs); CP16(bd + 16, bs + 8);
        CPCOMMIT();
    };

    int T = K >> 5;
    load_tile(0, 0);

    for (int t = 0; t < T; t++) {
        int buf = t & 1;
        CPWAIT0();
        __syncthreads();
        if (t + 1 < T) load_tile(t + 1, buf ^ 1);

        uint32_t a_base = (uint32_t)__cvta_generic_to_shared(
            &As[buf][wm + lrow][lsel]);
        uint32_t b_base = (uint32_t)__cvta_generic_to_shared(
            &Bs[buf][wn + lrow][lsel]);

        #pragma unroll
        for (int ks = 0; ks < 32; ks += 16) {
            uint32_t af[4][4], bf[4][2];
            #pragma unroll
            for (int im = 0; im < 4; im++)
                LDSM4(af[im][0], af[im][1], af[im][2], af[im][3],
                      a_base + im * 1280 + ks * 2);
            #pragma unroll
            for (int p = 0; p < 2; p++) {
                uint32_t r0, r1, r2, r3;
                LDSM4(r0, r1, r2, r3, b_base + p * 1280 + ks * 2);
                bf[2*p    ][0] = r0; bf[2*p + 1][0] = r1;
                bf[2*p    ][1] = r2; bf[2*p + 1][1] = r3;
            }
            #pragma unroll
            for (int im = 0; im < 4; im++)
                #pragma unroll
                for (int jn = 0; jn < 4; jn++) {
                    asm volatile(
                        "mma.sync.aligned.m16n8k16.row.col.f32.f16.f16.f32 "
                        "{%0,%1,%2,%3}, {%4,%5,%6,%7}, {%8,%9}, {%0,%1,%2,%3};\n"
                        : "+f"(acc[im][jn][0]), "+f"(acc[im][jn][1]),
                          "+f"(acc[im][jn][2]), "+f"(acc[im][jn][3])
                        : "r"(af[im][0]), "r"(af[im][1]),
                          "r"(af[im][2]), "r"(af[im][3]),
                          "r"(bf[jn][0]), "r"(bf[jn][1]));
                }
        }
        __syncthreads();
    }

    // epilogue
    float* Cf = (float*)Cv;
    __half* Ch = (__half*)Cv;
    #pragma unroll
    for (int im = 0; im < 4; im++) {
        #pragma unroll
        for (int jn = 0; jn < 4; jn++) {
            int m = bm + wm + im * 16 + gid;
            int n = bn + wn + jn * 8 + ctig * 2;
            float2 bb = *(const float2*)(bias + n);
            float v0 = acc[im][jn][0] + bb.x;
            float v1 = acc[im][jn][1] + bb.y;
            float v2 = acc[im][jn][2] + bb.x;
            float v3 = acc[im][jn][3] + bb.y;
            if (EPI == 1 || (EPI == 4 && n >= 3 * D_MODEL)) {
                v0 = 1.f / (1.f + expf(-v0));
                v1 = 1.f / (1.f + expf(-v1));
                v2 = 1.f / (1.f + expf(-v2));
                v3 = 1.f / (1.f + expf(-v3));
            } else if (EPI == 2) {
                float2 r0 = *(const float2*)(Res + (size_t)m * N + n);
                float2 r1 = *(const float2*)(Res + (size_t)(m + 8) * N + n);
                v0 += r0.x; v1 += r0.y; v2 += r1.x; v3 += r1.y;
            } else if (EPI == 3) {
                const float c = 0.70710678118654752f;
                v0 = 0.5f * v0 * (1.f + erff(v0 * c));
                v1 = 0.5f * v1 * (1.f + erff(v1 * c));
                v2 = 0.5f * v2 * (1.f + erff(v2 * c));
                v3 = 0.5f * v3 * (1.f + erff(v3 * c));
            }
            if (OUTH) {
                *(__half2*)(Ch + (size_t)m * N + n)       = __floats2half2_rn(v0, v1);
                *(__half2*)(Ch + (size_t)(m + 8) * N + n) = __floats2half2_rn(v2, v3);
            } else {
                *(float2*)(Cf + (size_t)m * N + n)       = make_float2(v0, v1);
                *(float2*)(Cf + (size_t)(m + 8) * N + n) = make_float2(v2, v3);
            }
        }
    }
}

// ---------------- Retention scan (chunked associative scan) ---------------
// qkvg layout: row-major [MROWS][4096], cols [q | k | v | g]
__device__ __forceinline__ void unit_decompose(int tid, int bx,
                                               int& b, int& h, int& chunk, int& d) {
    d = tid & 63;
    int unit = bx * 4 + (tid >> 6);
    chunk = unit & (NCHUNK - 1);
    int bh = unit >> 4;
    h = bh & (NHEADS - 1);
    b = bh >> 4;
}

__global__ void scan_partial(const float* __restrict__ dlogit) {
    int b, h, chunk, d;
    unit_decompose(threadIdx.x, blockIdx.x, b, h, chunk, d);
    float decay = 1.f / (1.f + expf(-dlogit[h]));
    float p = 0.f;
    size_t base = ((size_t)(b * SEQL + chunk * CLEN)) * QKVG_N + h * DHEAD + d;
    const __half* kp = g_qkvg + base + D_MODEL;
    const __half* vp = g_qkvg + base + 2 * D_MODEL;
    #pragma unroll 4
    for (int i = 0; i < CLEN; i++) {
        size_t o = (size_t)i * QKVG_N;
        p = decay * p + __half2float(kp[o]) * __half2float(vp[o]);
    }
    int bh = b * NHEADS + h;
    g_P[(bh * NCHUNK + chunk) * DHEAD + d] = p;
}

__global__ void scan_final(const float* __restrict__ dlogit) {
    int b, h, chunk, d;
    unit_decompose(threadIdx.x, blockIdx.x, b, h, chunk, d);
    float decay = 1.f / (1.f + expf(-dlogit[h]));
    float dCL = powf(decay, (float)CLEN);
    int bh = b * NHEADS + h;
    float s = 0.f;
    for (int j = 0; j < chunk; j++)
        s = dCL * s + g_P[(bh * NCHUNK + j) * DHEAD + d];
    const float scale = 0.125f;   // DHEAD^-0.5
    int row0 = b * SEQL + chunk * CLEN;
    size_t base = (size_t)row0 * QKVG_N + h * DHEAD + d;
    const __half* qp = g_qkvg + base;
    const __half* kp = g_qkvg + base + D_MODEL;
    const __half* vp = g_qkvg + base + 2 * D_MODEL;
    const __half* gp = g_qkvg + base + 3 * D_MODEL;
    __half* ap = g_attn + (size_t)row0 * D_MODEL + h * DHEAD + d;
    #pragma unroll 4
    for (int i = 0; i < CLEN; i++) {
        size_t o = (size_t)i * QKVG_N;
        s = decay * s + __half2float(kp[o]) * __half2float(vp[o]);
        float r = __half2float(gp[o]) * __half2float(qp[o]) * s * scale;
        ap[(size_t)i * D_MODEL] = __float2half_rn(r);
    }
}

// ---------------- launch ---------------------------------------------------
extern "C" void kernel_launch(void* const* d_in, const int* in_sizes, int n_in,
                              void* d_out, int out_size) {
    const float* x      = (const float*)d_in[0];
    const float* ln1_g  = (const float*)d_in[1];
    const float* ln1_b  = (const float*)d_in[2];
    const float* Wq     = (const float*)d_in[3];
    const float* bq     = (const float*)d_in[4];
    const float* Wk     = (const float*)d_in[5];
    const float* bk     = (const float*)d_in[6];
    const float* Wv     = (const float*)d_in[7];
    const float* bv     = (const float*)d_in[8];
    const float* Wg     = (const float*)d_in[9];
    const float* bg     = (const float*)d_in[10];
    const float* dlogit = (const float*)d_in[11];
    const float* Wo     = (const float*)d_in[12];
    const float* bo     = (const float*)d_in[13];
    const float* ln2_g  = (const float*)d_in[14];
    const float* ln2_b  = (const float*)d_in[15];
    const float* W1     = (const float*)d_in[16];
    const float* b1     = (const float*)d_in[17];
    const float* W2     = (const float*)d_in[18];
    const float* b2     = (const float*)d_in[19];
    float* out = (float*)d_out;

    float  *x2, *bqkvg;
    __half *y, *attn, *h, *ff1, *qkvg;
    __half *wtqkvg, *wto, *wt1, *wt2;
    cudaGetSymbolAddress((void**)&qkvg,   g_qkvg);
    cudaGetSymbolAddress((void**)&x2,     g_x2);
    cudaGetSymbolAddress((void**)&y,      g_y);
    cudaGetSymbolAddress((void**)&attn,   g_attn);
    cudaGetSymbolAddress((void**)&h,      g_h);
    cudaGetSymbolAddress((void**)&ff1,    g_ff1);
    cudaGetSymbolAddress((void**)&bqkvg,  g_bqkvg);
    cudaGetSymbolAddress((void**)&wtqkvg, g_wtqkvg);
    cudaGetSymbolAddress((void**)&wto,    g_wto);
    cudaGetSymbolAddress((void**)&wt1,    g_wt1);
    cudaGetSymbolAddress((void**)&wt2,    g_wt2);

    transpose_all<<<13312, dim3(32, 32)>>>(Wq, Wk, Wv, Wg, Wo, W1, W2);
    pack_bias<<<QKVG_N/256, 256>>>(bq, bk, bv, bg, bqkvg);

    dim3 gQ(QKVG_N / 128, MROWS / 128);   // 32 x 128
    dim3 gD(D_MODEL / 128, MROWS / 128);  //  8 x 128
    dim3 gF(DFF / 128,     MROWS / 128);  // 32 x 128

    ln_kernel<<<MROWS, 256>>>(x, ln1_g, ln1_b, y);

    hgemm<4,1><<<gQ, 256>>>(y, wtqkvg, bqkvg, nullptr, qkvg, D_MODEL, QKVG_N);

    scan_partial<<<256, 256>>>(dlogit);
    scan_final  <<<256, 256>>>(dlogit);

    hgemm<2,0><<<gD, 256>>>(attn, wto, bo, x, x2, D_MODEL, D_MODEL);

    ln_kernel<<<MROWS, 256>>>(x2, ln2_g, ln2_b, h);

    hgemm<3,1><<<gF, 256>>>(h,   wt1, b1, nullptr, ff1, D_MODEL, DFF);
    hgemm<2,0><<<gD, 256>>>(ff1, wt2, b2, x2,      out, DFF,     D_MODEL);
}

// round 13
// speedup vs baseline: 5.4919x; 1.0948x over previous
#include <cuda_runtime.h>
#include <cuda_fp16.h>
#include <math.h>
#include <stdint.h>

#define D_MODEL 1024
#define NHEADS 16
#define DHEAD 64
#define BATCH 4
#define SEQL 4096
#define MROWS (BATCH*SEQL)      /* 16384 */
#define DFF (4*D_MODEL)         /* 4096  */
#define QKVG_N (4*D_MODEL)      /* 4096  */
#define EPSLN 1e-5f
#define NCHUNK 16
#define CLEN (SEQL/NCHUNK)      /* 256   */

// ---------------- scratch (device globals; no allocation allowed) ----------
__device__ __half g_qkvg[(size_t)MROWS*QKVG_N];  // cols: [q | k | v | g]
__device__ float  g_x2  [MROWS*D_MODEL];
__device__ __half g_y   [MROWS*D_MODEL];
__device__ __half g_attn[MROWS*D_MODEL];
__device__ __half g_h   [MROWS*D_MODEL];
__device__ __half g_ff1 [(size_t)MROWS*DFF];
__device__ float  g_P   [BATCH*NHEADS*NCHUNK*DHEAD];
__device__ float  g_bqkvg[QKVG_N];
// transposed fp16 weights [N,K]
__device__ __half g_wtqkvg[(size_t)QKVG_N*D_MODEL];
__device__ __half g_wto [D_MODEL*D_MODEL];
__device__ __half g_wt1 [(size_t)D_MODEL*DFF];
__device__ __half g_wt2 [(size_t)DFF*D_MODEL];

#define CP16(dst, src) asm volatile( \
    "cp.async.cg.shared.global [%0], [%1], 16;\n" :: "r"(dst), "l"(src))
#define CPCOMMIT() asm volatile("cp.async.commit_group;\n" ::: "memory")
#define CPWAIT0()  asm volatile("cp.async.wait_group 0;\n" ::: "memory")
#define LDSM4(r0, r1, r2, r3, addr) asm volatile( \
    "ldmatrix.sync.aligned.m8n8.x4.shared.b16 {%0,%1,%2,%3}, [%4];" \
    : "=r"(r0), "=r"(r1), "=r"(r2), "=r"(r3) : "r"(addr))

// bank-swizzle value for a row (16B units): v(r) = ((r>>1)&3) ^ ((r>>3)&1)
__device__ __forceinline__ uint32_t swz(int r) {
    return (uint32_t)((((r >> 1) & 3) ^ ((r >> 3) & 1)) * 16);
}

// ---------------- all weight transposes in ONE launch -----------------------
__global__ void transpose_all(const float* __restrict__ Wq, const float* __restrict__ Wk,
                              const float* __restrict__ Wv, const float* __restrict__ Wg,
                              const float* __restrict__ Wo, const float* __restrict__ W1,
                              const float* __restrict__ W2) {
    __shared__ float t[32][33];
    int id = blockIdx.x;
    const float* W; __half* Wt; int K, N, bx, by;
    __half *wtqkvg = g_wtqkvg, *wto = g_wto, *wt1 = g_wt1, *wt2 = g_wt2;
    if (id < 4096) {
        int seg = id >> 10, r = id & 1023;
        const float* srcs[4] = {Wq, Wk, Wv, Wg};
        W = srcs[seg];
        Wt = wtqkvg + (size_t)seg * D_MODEL * D_MODEL;
        K = D_MODEL; N = D_MODEL; bx = r & 31; by = r >> 5;
    } else if (id < 5120) {
        int r = id - 4096;
        W = Wo; Wt = wto; K = D_MODEL; N = D_MODEL; bx = r & 31; by = r >> 5;
    } else if (id < 9216) {
        int r = id - 5120;
        W = W1; Wt = wt1; K = D_MODEL; N = DFF; bx = r & 127; by = r >> 7;
    } else {
        int r = id - 9216;
        W = W2; Wt = wt2; K = DFF; N = D_MODEL; bx = r & 31; by = r >> 5;
    }
    int n0 = bx * 32, k0 = by * 32;
    int tx = threadIdx.x, ty = threadIdx.y;
    t[ty][tx] = W[(size_t)(k0 + ty) * N + n0 + tx];
    __syncthreads();
    Wt[(size_t)(n0 + ty) * K + k0 + tx] = __float2half_rn(t[tx][ty]);
}

__global__ void pack_bias(const float* __restrict__ bq, const float* __restrict__ bk,
                          const float* __restrict__ bv, const float* __restrict__ bg,
                          float* __restrict__ o) {
    int i = blockIdx.x * 256 + threadIdx.x;
    float r;
    if      (i < 1024) r = bq[i];
    else if (i < 2048) r = bk[i - 1024];
    else if (i < 3072) r = bv[i - 2048];
    else               r = bg[i - 3072];
    o[i] = r;
}

// ---------------- LayerNorm: one block per row, out = fp16 ------------------
__global__ void ln_kernel(const float* __restrict__ x,
                          const float* __restrict__ gw,
                          const float* __restrict__ bw,
                          __half* __restrict__ out) {
    int row = blockIdx.x;
    int t = threadIdx.x;
    const float4* xr = (const float4*)(x + (size_t)row * D_MODEL);
    float4 v = xr[t];
    float s  = v.x + v.y + v.z + v.w;
    float ss = v.x*v.x + v.y*v.y + v.z*v.z + v.w*v.w;
    #pragma unroll
    for (int o = 16; o > 0; o >>= 1) {
        s  += __shfl_xor_sync(0xFFFFFFFFu, s,  o);
        ss += __shfl_xor_sync(0xFFFFFFFFu, ss, o);
    }
    __shared__ float red[2][8];
    int warp = t >> 5, lane = t & 31;
    if (lane == 0) { red[0][warp] = s; red[1][warp] = ss; }
    __syncthreads();
    if (t == 0) {
        float a = 0.f, c = 0.f;
        #pragma unroll
        for (int i = 0; i < 8; i++) { a += red[0][i]; c += red[1][i]; }
        float mu  = a * (1.f / D_MODEL);
        float var = c * (1.f / D_MODEL) - mu * mu;
        red[0][0] = mu;
        red[1][0] = rsqrtf(var + EPSLN);
    }
    __syncthreads();
    float mu = red[0][0], rs = red[1][0];
    float4 gv = ((const float4*)gw)[t];
    float4 bv = ((const float4*)bw)[t];
    __half2 h0 = __floats2half2_rn((v.x - mu) * rs * gv.x + bv.x,
                                   (v.y - mu) * rs * gv.y + bv.y);
    __half2 h1 = __floats2half2_rn((v.z - mu) * rs * gv.z + bv.z,
                                   (v.w - mu) * rs * gv.w + bv.w);
    __half2* op = (__half2*)(out + (size_t)row * D_MODEL + t * 4);
    op[0] = h0;
    op[1] = h1;
}

// ---------------- FP16 tensor-core GEMM -------------------------------------
// 128x128 block tile, BK=32, 256 threads (8 warps 2x4), warp tile 64x32,
// mma.sync.m16n8k16.f16 fp32-acc, xor-swizzled 64B-row smem (conflict-free
// ldmatrix.x4), cp.async double buffer, single barrier per k-tile.
// EPI: 0 bias, 1 bias+sigmoid, 2 bias+residual, 3 bias+gelu,
//      4 bias + sigmoid only for n >= 3*D_MODEL (fused QKVG epilogue)
// OUTH: 1 -> C fp16, else fp32.
template <int EPI, int OUTH>
__global__ __launch_bounds__(256, 2) void hgemm(
        const __half* __restrict__ A, const __half* __restrict__ Bt,
        const float* __restrict__ bias, const float* __restrict__ Res,
        void* __restrict__ Cv, int K, int N) {
    __shared__ __half As[2][128][32];   // 64B rows, xor-swizzled chunks
    __shared__ __half Bs[2][128][32];

    int tid  = threadIdx.x;
    int bm   = blockIdx.y * 128, bn = blockIdx.x * 128;
    int warp = tid >> 5, lane = tid & 31;
    int wm   = (warp >> 2) * 64;
    int wn   = (warp & 3) * 32;
    int gid  = lane >> 2, ctig = lane & 3;
    int lrow = lane & 15, lsel2 = (lane >> 4) * 16;   // byte offset 0/16
    uint32_t xv = swz(lrow);

    int l_row = tid >> 1;               // store row 0..127
    int c0    = (tid & 1) * 2;          // chunk 0 or 2
    uint32_t xvr = swz(l_row);

    float acc[4][4][4];
    #pragma unroll
    for (int i = 0; i < 4; i++)
        #pragma unroll
        for (int j = 0; j < 4; j++)
            #pragma unroll
            for (int r = 0; r < 4; r++) acc[i][j][r] = 0.f;

    const __half* Ag = A  + (size_t)(bm + l_row) * K + c0 * 8;
    const __half* Bg = Bt + (size_t)(bn + l_row) * K + c0 * 8;

    uint32_t as_base = (uint32_t)__cvta_generic_to_shared(&As[0][0][0]);
    uint32_t bs_base = (uint32_t)__cvta_generic_to_shared(&Bs[0][0][0]);

    auto load_tile = [&](int t, int buf) {
        int k0 = t * 32;
        uint32_t arow = as_base + buf * 8192 + l_row * 64;
        CP16(arow + (((uint32_t)(c0    * 16)) ^ xvr), Ag + k0);
        CP16(arow + (((uint32_t)((c0+1)* 16)) ^ xvr), Ag + k0 + 8);
        uint32_t brow = bs_base + buf * 8192 + l_row * 64;
        CP16(brow + (((uint32_t)(c0    * 16)) ^ xvr), Bg + k0);
        CP16(brow + (((uint32_t)((c0+1)* 16)) ^ xvr), Bg + k0 + 8);
        CPCOMMIT();
    };

    int T = K >> 5;
    load_tile(0, 0);

    for (int t = 0; t < T; t++) {
        int buf = t & 1;
        CPWAIT0();
        __syncthreads();
        if (t + 1 < T) load_tile(t + 1, buf ^ 1);

        uint32_t a_row = as_base + buf * 8192 + (wm + lrow) * 64;
        uint32_t b_row = bs_base + buf * 8192 + (wn + lrow) * 64;

        #pragma unroll
        for (int ks = 0; ks < 32; ks += 16) {
            uint32_t off = ((uint32_t)(lsel2 + ks * 2)) ^ xv;
            uint32_t af[4][4], bf[4][2];
            #pragma unroll
            for (int im = 0; im < 4; im++)
                LDSM4(af[im][0], af[im][1], af[im][2], af[im][3],
                      a_row + im * 1024 + off);
            #pragma unroll
            for (int p = 0; p < 2; p++) {
                uint32_t r0, r1, r2, r3;
                LDSM4(r0, r1, r2, r3, b_row + p * 1024 + off);
                bf[2*p    ][0] = r0; bf[2*p + 1][0] = r1;
                bf[2*p    ][1] = r2; bf[2*p + 1][1] = r3;
            }
            #pragma unroll
            for (int im = 0; im < 4; im++)
                #pragma unroll
                for (int jn = 0; jn < 4; jn++) {
                    asm volatile(
                        "mma.sync.aligned.m16n8k16.row.col.f32.f16.f16.f32 "
                        "{%0,%1,%2,%3}, {%4,%5,%6,%7}, {%8,%9}, {%0,%1,%2,%3};\n"
                        : "+f"(acc[im][jn][0]), "+f"(acc[im][jn][1]),
                          "+f"(acc[im][jn][2]), "+f"(acc[im][jn][3])
                        : "r"(af[im][0]), "r"(af[im][1]),
                          "r"(af[im][2]), "r"(af[im][3]),
                          "r"(bf[jn][0]), "r"(bf[jn][1]));
                }
        }
    }

    // epilogue
    float* Cf = (float*)Cv;
    __half* Ch = (__half*)Cv;
    #pragma unroll
    for (int im = 0; im < 4; im++) {
        #pragma unroll
        for (int jn = 0; jn < 4; jn++) {
            int m = bm + wm + im * 16 + gid;
            int n = bn + wn + jn * 8 + ctig * 2;
            float2 bb = *(const float2*)(bias + n);
            float v0 = acc[im][jn][0] + bb.x;
            float v1 = acc[im][jn][1] + bb.y;
            float v2 = acc[im][jn][2] + bb.x;
            float v3 = acc[im][jn][3] + bb.y;
            if (EPI == 1 || (EPI == 4 && n >= 3 * D_MODEL)) {
                v0 = 1.f / (1.f + expf(-v0));
                v1 = 1.f / (1.f + expf(-v1));
                v2 = 1.f / (1.f + expf(-v2));
                v3 = 1.f / (1.f + expf(-v3));
            } else if (EPI == 2) {
                float2 r0 = *(const float2*)(Res + (size_t)m * N + n);
                float2 r1 = *(const float2*)(Res + (size_t)(m + 8) * N + n);
                v0 += r0.x; v1 += r0.y; v2 += r1.x; v3 += r1.y;
            } else if (EPI == 3) {
                const float c = 0.70710678118654752f;
                v0 = 0.5f * v0 * (1.f + erff(v0 * c));
                v1 = 0.5f * v1 * (1.f + erff(v1 * c));
                v2 = 0.5f * v2 * (1.f + erff(v2 * c));
                v3 = 0.5f * v3 * (1.f + erff(v3 * c));
            }
            if (OUTH) {
                *(__half2*)(Ch + (size_t)m * N + n)       = __floats2half2_rn(v0, v1);
                *(__half2*)(Ch + (size_t)(m + 8) * N + n) = __floats2half2_rn(v2, v3);
            } else {
                *(float2*)(Cf + (size_t)m * N + n)       = make_float2(v0, v1);
                *(float2*)(Cf + (size_t)(m + 8) * N + n) = make_float2(v2, v3);
            }
        }
    }
}

// ---------------- Retention scan (chunked associative scan) ---------------
__device__ __forceinline__ void unit_decompose(int tid, int bx,
                                               int& b, int& h, int& chunk, int& d) {
    d = tid & 63;
    int unit = bx * 4 + (tid >> 6);
    chunk = unit & (NCHUNK - 1);
    int bh = unit >> 4;
    h = bh & (NHEADS - 1);
    b = bh >> 4;
}

__global__ void scan_partial(const float* __restrict__ dlogit) {
    int b, h, chunk, d;
    unit_decompose(threadIdx.x, blockIdx.x, b, h, chunk, d);
    float decay = 1.f / (1.f + expf(-dlogit[h]));
    float p = 0.f;
    size_t base = ((size_t)(b * SEQL + chunk * CLEN)) * QKVG_N + h * DHEAD + d;
    const __half* kp = g_qkvg + base + D_MODEL;
    const __half* vp = g_qkvg + base + 2 * D_MODEL;
    #pragma unroll 4
    for (int i = 0; i < CLEN; i++) {
        size_t o = (size_t)i * QKVG_N;
        p = decay * p + __half2float(kp[o]) * __half2float(vp[o]);
    }
    int bh = b * NHEADS + h;
    g_P[(bh * NCHUNK + chunk) * DHEAD + d] = p;
}

__global__ void scan_final(const float* __restrict__ dlogit) {
    int b, h, chunk, d;
    unit_decompose(threadIdx.x, blockIdx.x, b, h, chunk, d);
    float decay = 1.f / (1.f + expf(-dlogit[h]));
    float dCL = powf(decay, (float)CLEN);
    int bh = b * NHEADS + h;
    float s = 0.f;
    for (int j = 0; j < chunk; j++)
        s = dCL * s + g_P[(bh * NCHUNK + j) * DHEAD + d];
    const float scale = 0.125f;   // DHEAD^-0.5
    int row0 = b * SEQL + chunk * CLEN;
    size_t base = (size_t)row0 * QKVG_N + h * DHEAD + d;
    const __half* qp = g_qkvg + base;
    const __half* kp = g_qkvg + base + D_MODEL;
    const __half* vp = g_qkvg + base + 2 * D_MODEL;
    const __half* gp = g_qkvg + base + 3 * D_MODEL;
    __half* ap = g_attn + (size_t)row0 * D_MODEL + h * DHEAD + d;
    #pragma unroll 4
    for (int i = 0; i < CLEN; i++) {
        size_t o = (size_t)i * QKVG_N;
        s = decay * s + __half2float(kp[o]) * __half2float(vp[o]);
        float r = __half2float(gp[o]) * __half2float(qp[o]) * s * scale;
        ap[(size_t)i * D_MODEL] = __float2half_rn(r);
    }
}

// ---------------- launch ---------------------------------------------------
extern "C" void kernel_launch(void* const* d_in, const int* in_sizes, int n_in,
                              void* d_out, int out_size) {
    const float* x      = (const float*)d_in[0];
    const float* ln1_g  = (const float*)d_in[1];
    const float* ln1_b  = (const float*)d_in[2];
    const float* Wq     = (const float*)d_in[3];
    const float* bq     = (const float*)d_in[4];
    const float* Wk     = (const float*)d_in[5];
    const float* bk     = (const float*)d_in[6];
    const float* Wv     = (const float*)d_in[7];
    const float* bv     = (const float*)d_in[8];
    const float* Wg     = (const float*)d_in[9];
    const float* bg     = (const float*)d_in[10];
    const float* dlogit = (const float*)d_in[11];
    const float* Wo     = (const float*)d_in[12];
    const float* bo     = (const float*)d_in[13];
    const float* ln2_g  = (const float*)d_in[14];
    const float* ln2_b  = (const float*)d_in[15];
    const float* W1     = (const float*)d_in[16];
    const float* b1     = (const float*)d_in[17];
    const float* W2     = (const float*)d_in[18];
    const float* b2     = (const float*)d_in[19];
    float* out = (float*)d_out;

    float  *x2, *bqkvg;
    __half *y, *attn, *h, *ff1, *qkvg;
    __half *wtqkvg, *wto, *wt1, *wt2;
    cudaGetSymbolAddress((void**)&qkvg,   g_qkvg);
    cudaGetSymbolAddress((void**)&x2,     g_x2);
    cudaGetSymbolAddress((void**)&y,      g_y);
    cudaGetSymbolAddress((void**)&attn,   g_attn);
    cudaGetSymbolAddress((void**)&h,      g_h);
    cudaGetSymbolAddress((void**)&ff1,    g_ff1);
    cudaGetSymbolAddress((void**)&bqkvg,  g_bqkvg);
    cudaGetSymbolAddress((void**)&wtqkvg, g_wtqkvg);
    cudaGetSymbolAddress((void**)&wto,    g_wto);
    cudaGetSymbolAddress((void**)&wt1,    g_wt1);
    cudaGetSymbolAddress((void**)&wt2,    g_wt2);

    transpose_all<<<13312, dim3(32, 32)>>>(Wq, Wk, Wv, Wg, Wo, W1, W2);
    pack_bias<<<QKVG_N/256, 256>>>(bq, bk, bv, bg, bqkvg);

    dim3 gQ(QKVG_N / 128, MROWS / 128);   // 32 x 128
    dim3 gD(D_MODEL / 128, MROWS / 128);  //  8 x 128
    dim3 gF(DFF / 128,     MROWS / 128);  // 32 x 128

    ln_kernel<<<MROWS, 256>>>(x, ln1_g, ln1_b, y);

    hgemm<4,1><<<gQ, 256>>>(y, wtqkvg, bqkvg, nullptr, qkvg, D_MODEL, QKVG_N);

    scan_partial<<<256, 256>>>(dlogit);
    scan_final  <<<256, 256>>>(dlogit);

    hgemm<2,0><<<gD, 256>>>(attn, wto, bo, x, x2, D_MODEL, D_MODEL);

    ln_kernel<<<MROWS, 256>>>(x2, ln2_g, ln2_b, h);

    hgemm<3,1><<<gF, 256>>>(h,   wt1, b1, nullptr, ff1, D_MODEL, DFF);
    hgemm<2,0><<<gD, 256>>>(ff1, wt2, b2, x2,      out, DFF,     D_MODEL);
}